// round 15
// baseline (speedup 1.0000x reference)
#include <cuda_runtime.h>
#include <cuda_fp16.h>
#include <math.h>
#include <stdint.h>

#define Bb 16
#define Ll 512
#define Dd 512
#define Nn 3
#define Hh 8
#define DH 64
#define AH 256
#define KHALF 7

#define BLD 4194304L        // Bb*Ll*Dd
#define CTN 12582912L       // 8192*1536 per n
#define CTSZ 37748736L      // 3 * CTN

// ---------------- scratch ------------------------------------------------------
__device__ __half g_seg[BLD];
__device__ __half g_WH[7864320];                  // fp16, tiled 32x128 blocks
__device__ __half g_B1[3*BLD];
__device__ __half g_M [3*BLD];
__device__ __half g_CT[CTSZ];                     // [n][8192][1536] mq|mv|mk
__device__ __half g_A [BLD];
__device__ float g_H2[Bb*Nn*Dd];
__device__ float g_SW[Bb*Nn];
__device__ float g_biasC[8*1536];

#define OFF_HW1 0L
#define OFF_HW3 786432L
#define OFF_LCV 1572864L
#define OFF_GCV 6291456L

// ---------------- PTX helpers --------------------------------------------------
__device__ __forceinline__ uint32_t smem_u32(const void* p) {
    uint32_t a;
    asm("{ .reg .u64 t; cvta.to.shared.u64 t, %1; cvt.u32.u64 %0, t; }" : "=r"(a) : "l"(p));
    return a;
}
#define CPA16(dst, src) asm volatile( \
    "cp.async.ca.shared.global [%0], [%1], 16;" :: "r"(dst), "l"(__cvta_generic_to_global(src)))
#define CPA_COMMIT() asm volatile("cp.async.commit_group;" ::: "memory")
#define CPA_WAIT1()  asm volatile("cp.async.wait_group 1;" ::: "memory")

#define BULK(dst, src, sz, mb) asm volatile( \
    "cp.async.bulk.shared::cta.global.mbarrier::complete_tx::bytes [%0], [%1], %2, [%3];" \
    :: "r"(dst), "l"(__cvta_generic_to_global(src)), "r"((uint32_t)(sz)), "r"(mb) : "memory")

#define MBAR_INIT(mb, c)   asm volatile("mbarrier.init.shared.b64 [%0], %1;" :: "r"(mb), "r"((uint32_t)(c)) : "memory")
#define MBAR_EXPECT(mb, tx) asm volatile("mbarrier.arrive.expect_tx.shared.b64 _, [%0], %1;" :: "r"(mb), "r"((uint32_t)(tx)) : "memory")
#define FENCE_ASYNC_SHARED() asm volatile("fence.proxy.async.shared::cta;" ::: "memory")
#define MBAR_WAIT(mb, ph) do { \
    uint32_t _m = (mb), _p = (ph), _d; \
    asm volatile("{\n\t.reg .pred p;\n\tmbarrier.try_wait.parity.acquire.cta.shared::cta.b64 p, [%1], %2;\n\tselp.b32 %0, 1, 0, p;\n\t}" \
        : "=r"(_d) : "r"(_m), "r"(_p) : "memory"); \
    if (!_d) { \
        asm volatile("{\n\t.reg .pred P1;\n\tWL_%=:\n\tmbarrier.try_wait.parity.acquire.cta.shared::cta.b64 P1, [%0], %1, 0x989680;\n\t@P1 bra.uni WD_%=;\n\tbra.uni WL_%=;\n\tWD_%=:\n\t}" \
            :: "r"(_m), "r"(_p) : "memory"); \
    } } while (0)

#define LDM_X4(r, a) asm volatile( \
    "ldmatrix.sync.aligned.m8n8.x4.shared.b16 {%0,%1,%2,%3}, [%4];" \
    : "=r"((r)[0]),"=r"((r)[1]),"=r"((r)[2]),"=r"((r)[3]) : "r"(a))
#define LDM_X4T(r, a) asm volatile( \
    "ldmatrix.sync.aligned.m8n8.x4.trans.shared.b16 {%0,%1,%2,%3}, [%4];" \
    : "=r"((r)[0]),"=r"((r)[1]),"=r"((r)[2]),"=r"((r)[3]) : "r"(a))
#define MMAF16(d, a, b) asm volatile( \
    "mma.sync.aligned.m16n8k16.row.col.f32.f16.f16.f32 " \
    "{%0,%1,%2,%3}, {%4,%5,%6,%7}, {%8,%9}, {%0,%1,%2,%3};" \
    : "+f"((d)[0]),"+f"((d)[1]),"+f"((d)[2]),"+f"((d)[3]) \
    : "r"((a)[0]),"r"((a)[1]),"r"((a)[2]),"r"((a)[3]), "r"((b)[0]),"r"((b)[1]))

__device__ __forceinline__ uint32_t packh2(float a, float b) {
    __half2 t = __floats2half2_rn(a, b);
    return *reinterpret_cast<uint32_t*>(&t);
}

// ---------------- merged prepass ------------------------------------------------
__global__ void prep_all_k(const float* __restrict__ seg,
                           const float* __restrict__ hw1, const float* __restrict__ hw3,
                           const float* __restrict__ lcW, const float* __restrict__ lvW,
                           const float* __restrict__ gcW, const float* __restrict__ gvW,
                           const float* __restrict__ lcb, const float* __restrict__ lvb,
                           const float* __restrict__ gcb, const float* __restrict__ gvb)
{
    long gstride = (long)gridDim.x * blockDim.x * 4;
    for (long i = ((long)blockIdx.x * blockDim.x + threadIdx.x) * 4; i < BLD; i += gstride) {
        float4 v = *reinterpret_cast<const float4*>(seg + i);
        uint2 o;
        o.x = packh2(v.x, v.y);
        o.y = packh2(v.z, v.w);
        *reinterpret_cast<uint2*>(g_seg + i) = o;
    }
    const float* srcs[6] = {hw1, hw3, lcW, lvW, gcW, gvW};
    const long  woff[6]  = {OFF_HW1, OFF_HW3, OFF_LCV, OFF_LCV, OFF_GCV, OFF_GCV};
    const int   C1s[6]   = {512, 512, 1024, 512, 1024, 512};
    const int   coff[6]  = {0, 0, 0, 1024, 0, 1024};
    const long  dss[6]   = {262144L, 262144L, 786432L, 786432L, 786432L, 786432L};
    const long  tots[6]  = {786432L, 786432L, 3145728L, 1572864L, 1048576L, 524288L};
    #pragma unroll 1
    for (int sg = 0; sg < 6; sg++) {
        const float* s = srcs[sg];
        int C1 = C1s[sg];
        long sS = 512L * C1;
        for (long i = ((long)blockIdx.x * blockDim.x + threadIdx.x) * 4; i < tots[sg];
             i += gstride) {
            float4 v = *reinterpret_cast<const float4*>(s + i);
            long sl = i / sS;
            long rem = i - sl * sS;
            int k = (int)(rem / C1), c = (int)(rem - (long)(rem / C1) * C1);
            int n = coff[sg] + c;
            long d = woff[sg] + sl * dss[sg] + ((long)((n >> 7) * 16 + (k >> 5))) * 4096
                   + (k & 31) * 128 + ((((n & 127) >> 3) ^ (k & 7)) << 3) + (n & 7);
            float vv[4] = {v.x, v.y, v.z, v.w};
            #pragma unroll
            for (int e = 0; e < 4; e++)
                g_WH[d + e] = __float2half_rn(vv[e]);
        }
    }
    for (long i = (long)blockIdx.x * blockDim.x + threadIdx.x; i < 8 * 1536;
         i += (long)gridDim.x * blockDim.x) {
        int slot = (int)(i / 1536), c = (int)(i % 1536);
        float v;
        if (slot < 6) v = (c < 1024) ? lcb[slot * 1024 + c] : lvb[slot * 512 + c - 1024];
        else {
            int s = slot - 6;
            v = (c < 1024) ? gcb[s * 1024 + c] : gvb[s * 512 + c - 1024];
        }
        g_biasC[slot * 1536 + c] = v;
    }
}

// ---------------- GEMM: fp16, BK=64, 2-stage pipeline, 2 CTAs/SM ---------------
#define A_SUB 10240
#define A_BYTES 20480
#define STAGE 53248
#define GSMEM 106520
__global__ void __launch_bounds__(256, 2) mma_gemm_k(
    const __half* __restrict__ A, const __half* __restrict__ WH,
    const float* __restrict__ bias, const float* __restrict__ H2,
    __half* __restrict__ C,
    int K, int lda, int ldc,
    long sAi, long sBi, long sCi, long sBias, int flags)
{
    extern __shared__ char dsm[];
    uint32_t sb0 = smem_u32(dsm);
    uint32_t mbar0 = sb0 + 2 * STAGE;

    int z = blockIdx.z;
    A  += z * sAi;
    WH += z * sBi;
    C  += z * sCi;
    if (bias) bias += z * sBias;

    int tid = threadIdx.x, lane = tid & 31, wid = tid >> 5;
    int wm = wid & 1, wn = wid >> 1;
    int m0 = blockIdx.y * 128;
    int bx = blockIdx.x, n0 = bx * 256;
    int nc = K / 64;
    int nk32 = K / 32;

    if (tid == 0) {
        MBAR_INIT(mbar0, 1); MBAR_INIT(mbar0 + 8, 1);
        FENCE_ASYNC_SHARED();
    }
    __syncthreads();

    auto fillA = [&](int c) {
        int k0 = c * 64;
        uint32_t st = sb0 + (c & 1) * STAGE;
        #pragma unroll
        for (int sub = 0; sub < 2; sub++) {
            #pragma unroll
            for (int it = 0; it < 2; it++) {
                int idx = tid + it * 256;
                int rr = idx >> 2, uu = idx & 3;
                CPA16(st + sub * A_SUB + rr * 80 + uu * 16,
                      A + (long)(m0 + rr) * lda + k0 + sub * 32 + uu * 8);
            }
        }
    };
    auto fillB = [&](int c) {
        uint32_t st = sb0 + (c & 1) * STAGE + A_BYTES;
        uint32_t mb = mbar0 + (c & 1) * 8;
        MBAR_EXPECT(mb, 32768u);
        long off0 = ((long)(bx * 2)     * nk32 + 2 * c) * 4096;
        long off1 = ((long)(bx * 2 + 1) * nk32 + 2 * c) * 4096;
        BULK(st,         WH + off0, 16384, mb);
        BULK(st + 16384, WH + off1, 16384, mb);
    };

    float acc[4][8][4] = {};

    fillA(0); CPA_COMMIT();
    fillA(1); CPA_COMMIT();
    if (tid == 0) { fillB(0); fillB(1); }

    int alr = lane & 15, alc = (lane >> 4) << 3;
    int btr = (lane & 7) + (((lane >> 3) & 1) << 3);
    int btcc = (lane >> 4) & 1;

    for (int c = 0; c < nc; c++) {
        CPA_WAIT1();
        MBAR_WAIT(mbar0 + (c & 1) * 8, (c >> 1) & 1);
        __syncthreads();

        uint32_t base = sb0 + (c & 1) * STAGE;

        #pragma unroll
        for (int kk = 0; kk < 4; kk++) {
            uint32_t ah[4][4], bh[8][2];
            uint32_t aA = base + (kk >> 1) * A_SUB +
                          (uint32_t)(((wm * 64 + alr) * 40 + (kk & 1) * 16 + alc) * 2);
            #pragma unroll
            for (int mt = 0; mt < 4; mt++)
                LDM_X4(ah[mt], aA + (uint32_t)(mt * 16 * 80));
            int krow = (kk & 1) * 16 + btr;
            uint32_t bB = base + A_BYTES + (wn >> 1) * 16384 + (kk >> 1) * 8192;
            #pragma unroll
            for (int p = 0; p < 4; p++) {
                int c16 = (wn & 1) * 8 + p * 2 + btcc;
                uint32_t ad = bB + (uint32_t)(krow * 256 + ((c16 ^ (krow & 7)) << 4));
                uint32_t r[4];
                LDM_X4T(r, ad);
                bh[2*p][0]=r[0]; bh[2*p][1]=r[1]; bh[2*p+1][0]=r[2]; bh[2*p+1][1]=r[3];
            }
            #pragma unroll
            for (int mt = 0; mt < 4; mt++)
                #pragma unroll
                for (int nt = 0; nt < 8; nt++)
                    MMAF16(acc[mt][nt], ah[mt], bh[nt]);
        }

        __syncthreads();
        if (c + 2 < nc) {
            fillA(c + 2);
            CPA_COMMIT();
            if (tid == 0) fillB(c + 2);
        } else {
            CPA_COMMIT();
        }
    }

    const float* H2b = (flags & 8) ? (H2 + ((long)(m0 >> 9) * Nn + z) * 512) : nullptr;

    #pragma unroll
    for (int mt = 0; mt < 4; mt++) {
        int row = m0 + wm * 64 + mt * 16 + (lane >> 2);
        #pragma unroll
        for (int nt = 0; nt < 8; nt++) {
            int col = n0 + wn * 64 + nt * 8 + (lane & 3) * 2;
            float d0 = acc[mt][nt][0], d1 = acc[mt][nt][1];
            float d2 = acc[mt][nt][2], d3 = acc[mt][nt][3];
            if (bias) {
                float b0 = bias[col], b1 = bias[col + 1];
                d0 += b0; d1 += b1; d2 += b0; d3 += b1;
            }
            if (flags & 2) {
                d0 = fmaxf(d0, 0.f); d1 = fmaxf(d1, 0.f);
                d2 = fmaxf(d2, 0.f); d3 = fmaxf(d3, 0.f);
            }
            if (H2b) {
                float f0 = H2b[col], f1 = H2b[col + 1];
                d0 *= f0; d1 *= f1; d2 *= f0; d3 *= f1;
            }
            long o0 = (long)row * ldc + col;
            long o1 = o0 + (long)8 * ldc;
            *reinterpret_cast<uint32_t*>(C + o0) = packh2(d0, d1);
            *reinterpret_cast<uint32_t*>(C + o1) = packh2(d2, d3);
        }
    }
}

// ---------------- flash global attention ---------------------------------------
#define FQ 0
#define FK 18432
#define FV 36864
#define FMSK 55296
#define FSMEM 57344
#define FLDQ 72

__global__ void __launch_bounds__(256, 1) flash_k(const float* __restrict__ mask,
                                                  float* __restrict__ outp)
{
    extern __shared__ char sm[];
    uint32_t sb = smem_u32(sm);
    float* mbias = reinterpret_cast<float*>(sm + FMSK);
    int tid = threadIdx.x, lane = tid & 31, w = tid >> 5;
    int b = blockIdx.y >> 3, h = blockIdx.y & 7;
    int l0 = blockIdx.x * 128;
    long base = (long)b * 512 * 1536;

    for (int i = tid; i < 1024; i += 256) {
        int row = i >> 3, u = i & 7;
        *reinterpret_cast<uint4*>(sm + FQ + row * 144 + u * 16) =
            *reinterpret_cast<const uint4*>(g_CT + base + (long)(l0 + row) * 1536 + 1024 + h * DH + u * 8);
    }
    for (int i = tid; i < 512; i += 256)
        mbias[i] = (mask[(long)b * 512 + i] != 0.f) ? 0.f : -1e9f;

    float O[8][4];
    #pragma unroll
    for (int i = 0; i < 8; i++)
        #pragma unroll
        for (int e = 0; e < 4; e++) O[i][e] = 0.f;
    float mrow[2] = {-1e30f, -1e30f}, lrow[2] = {0.f, 0.f};

    int alr = lane & 15, alc = (lane >> 4) << 3;
    int blr = (lane & 7) + (((lane >> 4) & 1) << 3), blc = ((lane >> 3) & 1) << 3;
    int btr = (lane & 7) + (((lane >> 3) & 1) << 3), btc = ((lane >> 4) & 1) << 3;
    int c0 = (lane & 3) * 2;

    for (int mi = 0; mi < 4; mi++) {
        int m0 = mi * 128;
        __syncthreads();
        for (int i = tid; i < 1024; i += 256) {
            int row = i >> 3, u = i & 7;
            long gq = base + (long)(m0 + row) * 1536 + h * DH + u * 8;
            *reinterpret_cast<uint4*>(sm + FK + row * 144 + u * 16) =
                *reinterpret_cast<const uint4*>(g_CT + gq);
            *reinterpret_cast<uint4*>(sm + FV + row * 144 + u * 16) =
                *reinterpret_cast<const uint4*>(g_CT + gq + 512);
        }
        __syncthreads();

        float S[16][4];
        #pragma unroll
        for (int i = 0; i < 16; i++)
            #pragma unroll
            for (int e = 0; e < 4; e++) S[i][e] = 0.f;

        #pragma unroll
        for (int kc = 0; kc < 4; kc++) {
            uint32_t q[4];
            LDM_X4(q, sb + FQ + (uint32_t)(((w * 16 + alr) * FLDQ + kc * 16 + alc) * 2));
            #pragma unroll
            for (int p = 0; p < 8; p++) {
                uint32_t kf[4];
                LDM_X4(kf, sb + FK + (uint32_t)(((p * 16 + blr) * FLDQ + kc * 16 + blc) * 2));
                uint32_t b0[2] = {kf[0], kf[1]}, b1[2] = {kf[2], kf[3]};
                MMAF16(S[2*p],   q, b0);
                MMAF16(S[2*p+1], q, b1);
            }
        }

        float cmax[2] = {-1e30f, -1e30f};
        #pragma unroll
        for (int nt = 0; nt < 16; nt++)
            #pragma unroll
            for (int e = 0; e < 4; e++) {
                int col = m0 + nt * 8 + c0 + (e & 1);
                float v = S[nt][e] * 0.125f + mbias[col];
                S[nt][e] = v;
                cmax[e >> 1] = fmaxf(cmax[e >> 1], v);
            }
        #pragma unroll
        for (int o = 1; o <= 2; o <<= 1) {
            cmax[0] = fmaxf(cmax[0], __shfl_xor_sync(0xffffffffu, cmax[0], o));
            cmax[1] = fmaxf(cmax[1], __shfl_xor_sync(0xffffffffu, cmax[1], o));
        }
        float mn0 = fmaxf(mrow[0], cmax[0]), mn1 = fmaxf(mrow[1], cmax[1]);
        float a0 = __expf(mrow[0] - mn0), a1 = __expf(mrow[1] - mn1);
        mrow[0] = mn0; mrow[1] = mn1;
        lrow[0] *= a0; lrow[1] *= a1;
        #pragma unroll
        for (int i = 0; i < 8; i++) {
            O[i][0] *= a0; O[i][1] *= a0; O[i][2] *= a1; O[i][3] *= a1;
        }
        #pragma unroll
        for (int nt = 0; nt < 16; nt++)
            #pragma unroll
            for (int e = 0; e < 4; e++) {
                float p = __expf(S[nt][e] - ((e < 2) ? mn0 : mn1));
                S[nt][e] = p;
                lrow[e >> 1] += p;
            }

        #pragma unroll
        for (int kc = 0; kc < 8; kc++) {
            uint32_t ph[4];
            ph[0] = packh2(S[2*kc][0],   S[2*kc][1]);
            ph[1] = packh2(S[2*kc][2],   S[2*kc][3]);
            ph[2] = packh2(S[2*kc+1][0], S[2*kc+1][1]);
            ph[3] = packh2(S[2*kc+1][2], S[2*kc+1][3]);
            #pragma unroll
            for (int p = 0; p < 4; p++) {
                uint32_t vh[4];
                LDM_X4T(vh, sb + FV + (uint32_t)(((kc * 16 + btr) * FLDQ + p * 16 + btc) * 2));
                uint32_t b0[2] = {vh[0], vh[1]}, b1[2] = {vh[2], vh[3]};
                MMAF16(O[2*p],   ph, b0);
                MMAF16(O[2*p+1], ph, b1);
            }
        }
    }

    #pragma unroll
    for (int o = 1; o <= 2; o <<= 1) {
        lrow[0] += __shfl_xor_sync(0xffffffffu, lrow[0], o);
        lrow[1] += __shfl_xor_sync(0xffffffffu, lrow[1], o);
    }
    float inv0 = 1.f / lrow[0], inv1 = 1.f / lrow[1];

    int r0g = l0 + w * 16 + (lane >> 2);
    #pragma unroll
    for (int nt = 0; nt < 8; nt++) {
        int col = h * DH + nt * 8 + c0;
        long o0 = ((long)b * 512 + r0g) * 512 + col;
        long o1 = o0 + 8 * 512;
        __half2 x0 = *reinterpret_cast<const __half2*>(g_A + o0);
        __half2 x1 = *reinterpret_cast<const __half2*>(g_A + o1);
        float d0 = __low2float(x0) + O[nt][0] * inv0;
        float d1 = __high2float(x0) + O[nt][1] * inv0;
        float d2 = __low2float(x1) + O[nt][2] * inv1;
        float d3 = __high2float(x1) + O[nt][3] * inv1;
        if (outp) {
            *reinterpret_cast<float2*>(outp + o0) = make_float2(d0, d1);
            *reinterpret_cast<float2*>(outp + o1) = make_float2(d2, d3);
        } else {
            *reinterpret_cast<uint32_t*>(g_A + o0) = packh2(d0, d1);
            *reinterpret_cast<uint32_t*>(g_A + o1) = packh2(d2, d3);
        }
    }
}

// ---------------- MMA banded local attention (band-pruned) ----------------------
#define LK2 0
#define LMQ2 18432
#define LMV2 39168
#define LBI2 59904
#define LSMEM 60480

__global__ void __launch_bounds__(256, 1) local_attn_k(const float* __restrict__ mask)
{
    extern __shared__ char sm[];
    uint32_t sb = smem_u32(sm);
    float* sBias = reinterpret_cast<float*>(sm + LBI2);
    int tid = threadIdx.x, lane = tid & 31, w = tid >> 5;
    int b = blockIdx.y >> 3, h = blockIdx.y & 7;
    int n = blockIdx.z;
    int l0 = blockIdx.x * 128;
    long base = (long)n * CTN + (long)b * 512 * 1536;

    for (int i = tid; i < 1024; i += 256) {
        int row = i >> 3, u = i & 7;
        *reinterpret_cast<uint4*>(sm + LK2 + row * 144 + u * 16) =
            *reinterpret_cast<const uint4*>(g_CT + base + (long)(l0 + row) * 1536 + 1024 + h * DH + u * 8);
    }
    for (int i = tid; i < 1152; i += 256) {
        int r = i >> 3, u = i & 7;
        int m = l0 - 8 + r;
        if (m >= 0 && m < 512) {
            long g = base + (long)m * 1536 + h * DH + u * 8;
            *reinterpret_cast<uint4*>(sm + LMQ2 + r * 144 + u * 16) =
                *reinterpret_cast<const uint4*>(g_CT + g);
            *reinterpret_cast<uint4*>(sm + LMV2 + r * 144 + u * 16) =
                *reinterpret_cast<const uint4*>(g_CT + g + 512);
        } else {
            uint4 z = make_uint4(0, 0, 0, 0);
            *reinterpret_cast<uint4*>(sm + LMQ2 + r * 144 + u * 16) = z;
            *reinterpret_cast<uint4*>(sm + LMV2 + r * 144 + u * 16) = z;
        }
    }
    for (int i = tid; i < 144; i += 256) {
        int m = l0 - 8 + i;
        sBias[i] = (m >= 0 && m < 512 && mask[(long)b * 512 + m] != 0.f) ? 0.f : -1e9f;
    }
    __syncthreads();

    int alr = lane & 15, alc = (lane >> 4) << 3;
    int blr = (lane & 7) + (((lane >> 4) & 1) << 3), blc = ((lane >> 3) & 1) << 3;
    int btr = (lane & 7) + (((lane >> 3) & 1) << 3), btc = ((lane >> 4) & 1) << 3;
    int c0 = (lane & 3) * 2;
    int r0 = w * 16 + (lane >> 2);

    float S[4][4];
    #pragma unroll
    for (int i = 0; i < 4; i++)
        #pragma unroll
        for (int e = 0; e < 4; e++) S[i][e] = 0.f;

    #pragma unroll
    for (int kc = 0; kc < 4; kc++) {
        uint32_t aq[4];
        LDM_X4(aq, sb + LK2 + (uint32_t)(((w * 16 + alr) * 72 + kc * 16 + alc) * 2));
        #pragma unroll
        for (int pi = 0; pi < 2; pi++) {
            int p = w + pi;
            uint32_t kf[4];
            LDM_X4(kf, sb + LMQ2 + (uint32_t)(((p * 16 + blr) * 72 + kc * 16 + blc) * 2));
            uint32_t b0[2] = {kf[0], kf[1]}, b1[2] = {kf[2], kf[3]};
            MMAF16(S[2*pi],   aq, b0);
            MMAF16(S[2*pi+1], aq, b1);
        }
    }

    float mx0 = -1e30f, mx1 = -1e30f;
    #pragma unroll
    for (int i = 0; i < 4; i++)
        #pragma unroll
        for (int e = 0; e < 4; e++) {
            int col = (w + (i >> 1)) * 16 + (i & 1) * 8 + c0 + (e & 1);
            int lr = (e < 2) ? r0 : (r0 + 8);
            float v = S[i][e] * 0.125f + sBias[col];
            if (col < lr + 1 || col > lr + 15) v = -1e30f;
            S[i][e] = v;
            if (e < 2) mx0 = fmaxf(mx0, v); else mx1 = fmaxf(mx1, v);
        }
    #pragma unroll
    for (int o = 1; o <= 2; o <<= 1) {
        mx0 = fmaxf(mx0, __shfl_xor_sync(0xffffffffu, mx0, o));
        mx1 = fmaxf(mx1, __shfl_xor_sync(0xffffffffu, mx1, o));
    }
    float s0 = 0.f, s1 = 0.f;
    #pragma unroll
    for (int i = 0; i < 4; i++)
        #pragma unroll
        for (int e = 0; e < 4; e++) {
            float p = __expf(S[i][e] - ((e < 2) ? mx0 : mx1));
            S[i][e] = p;
            if (e < 2) s0 += p; else s1 += p;
        }
    #pragma unroll
    for (int o = 1; o <= 2; o <<= 1) {
        s0 += __shfl_xor_sync(0xffffffffu, s0, o);
        s1 += __shfl_xor_sync(0xffffffffu, s1, o);
    }
    float inv0 = 1.f / s0, inv1 = 1.f / s1;

    float O[8][4];
    #pragma unroll
    for (int i = 0; i < 8; i++)
        #pragma unroll
        for (int e = 0; e < 4; e++) O[i][e] = 0.f;

    #pragma unroll
    for (int ki = 0; ki < 2; ki++) {
        int kc = w + ki;
        uint32_t ph[4];
        ph[0] = packh2(S[2*ki][0],   S[2*ki][1]);
        ph[1] = packh2(S[2*ki][2],   S[2*ki][3]);
        ph[2] = packh2(S[2*ki+1][0], S[2*ki+1][1]);
        ph[3] = packh2(S[2*ki+1][2], S[2*ki+1][3]);
        #pragma unroll
        for (int p = 0; p < 4; p++) {
            uint32_t vh[4];
            LDM_X4T(vh, sb + LMV2 + (uint32_t)(((kc * 16 + btr) * 72 + p * 16 + btc) * 2));
            uint32_t b0[2] = {vh[0], vh[1]}, b1[2] = {vh[2], vh[3]};
            MMAF16(O[2*p],   ph, b0);
            MMAF16(O[2*p+1], ph, b1);
        }
    }

    int gl = l0 + r0;
    #pragma unroll
    for (int nt = 0; nt < 8; nt++) {
        int col = h * DH + nt * 8 + c0;
        long o0 = (long)n * BLD + ((long)b * 512 + gl) * 512 + col;
        long o1 = o0 + 8 * 512;
        __half2 x0 = *reinterpret_cast<const __half2*>(g_M + o0);
        __half2 x1 = *reinterpret_cast<const __half2*>(g_M + o1);
        *reinterpret_cast<uint32_t*>(g_M + o0) =
            packh2(__low2float(x0) + O[nt][0] * inv0, __high2float(x0) + O[nt][1] * inv0);
        *reinterpret_cast<uint32_t*>(g_M + o1) =
            packh2(__low2float(x1) + O[nt][2] * inv1, __high2float(x1) + O[nt][3] * inv1);
    }
}

// ---------------- small kernels ------------------------------------------------
__global__ void h2_k(const float* __restrict__ se, const float* __restrict__ w2,
                     const float* __restrict__ b2)
{
    __shared__ float red[8][128];
    int bn = blockIdx.x;
    int n = bn % Nn;
    int h = blockIdx.y * 128 + threadIdx.x;
    int ty = threadIdx.y;
    const float* x = se + (long)bn * Dd;
    const float* w = w2 + (long)n * Dd * Dd + h;
    int d0 = ty * 64;
    float a0 = 0.f, a1 = 0.f, a2 = 0.f, a3 = 0.f;
    #pragma unroll 4
    for (int d = d0; d < d0 + 64; d += 4) {
        a0 = fmaf(x[d],     w[(long)d * Dd],       a0);
        a1 = fmaf(x[d + 1], w[(long)(d + 1) * Dd], a1);
        a2 = fmaf(x[d + 2], w[(long)(d + 2) * Dd], a2);
        a3 = fmaf(x[d + 3], w[(long)(d + 3) * Dd], a3);
    }
    red[ty][threadIdx.x] = (a0 + a1) + (a2 + a3);
    __syncthreads();
    if (ty == 0) {
        float acc = b2[n * Dd + h];
        #pragma unroll
        for (int e = 0; e < 8; e++) acc += red[e][threadIdx.x];
        g_H2[(long)bn * Dd + h] = fmaxf(acc, 0.f);
    }
}

__global__ void satt_k(const float* __restrict__ se, const float* __restrict__ w1,
                       const float* __restrict__ w2, float* __restrict__ out_tail)
{
    __shared__ float red[4][256];
    __shared__ float s1[256];
    __shared__ float alpha[Nn];
    int b = blockIdx.x, t = threadIdx.x, y = threadIdx.y;
    for (int n = 0; n < Nn; n++) {
        const float* x = se + ((long)b * Nn + n) * Dd;
        int d0 = y * 128;
        float a0 = 0.f, a1 = 0.f, a2 = 0.f, a3 = 0.f;
        #pragma unroll 4
        for (int d = d0; d < d0 + 128; d += 4) {
            a0 = fmaf(x[d],     w1[(long)d * AH + t],       a0);
            a1 = fmaf(x[d + 1], w1[(long)(d + 1) * AH + t], a1);
            a2 = fmaf(x[d + 2], w1[(long)(d + 2) * AH + t], a2);
            a3 = fmaf(x[d + 3], w1[(long)(d + 3) * AH + t], a3);
        }
        red[y][t] = (a0 + a1) + (a2 + a3);
        __syncthreads();
        if (y == 0) {
            float dot = red[0][t] + red[1][t] + red[2][t] + red[3][t];
            s1[t] = tanhf(dot) * w2[t];
        }
        __syncthreads();
        for (int o = 128; o; o >>= 1) {
            if (y == 0 && t < o) s1[t] += s1[t + o];
            __syncthreads();
        }
        if (y == 0 && t == 0) alpha[n] = s1[0];
        __syncthreads();
    }
    if (y == 0 && t == 0) {
        float mx = fmaxf(alpha[0], fmaxf(alpha[1], alpha[2]));
        float e[Nn], sum = 0.f;
        for (int n = 0; n < Nn; n++) { e[n] = expf(alpha[n] - mx); sum += e[n]; }
        for (int n = 0; n < Nn; n++) {
            float w = e[n] / sum;
            g_SW[b * Nn + n] = w;
            out_tail[b * Nn + n] = w;
        }
    }
}

__global__ void agg_k()
{
    long half_total = BLD / 2;
    long stride = (long)Ll * Dd / 2;
    for (long i = (long)blockIdx.x * blockDim.x + threadIdx.x; i < half_total;
         i += (long)gridDim.x * blockDim.x) {
        int b = (int)(i / stride);
        float a0 = 0.f, a1 = 0.f;
        #pragma unroll
        for (int n = 0; n < Nn; n++) {
            float sw = g_SW[b * Nn + n];
            __half2 v = *reinterpret_cast<const __half2*>(g_M + (long)n * BLD + i * 2);
            a0 = fmaf(sw, __low2float(v), a0);
            a1 = fmaf(sw, __high2float(v), a1);
        }
        *reinterpret_cast<uint32_t*>(g_A + i * 2) = packh2(a0, a1);
    }
}

// ---------------- host orchestration ------------------------------------------
static void mgemm(const __half* A, const __half* WH,
                  const float* bias, const float* H2, __half* C,
                  int N, int K, int lda, int ldc, int batches,
                  long sAi, long sBi, long sCi, long sBias, int flags)
{
    dim3 grid(N / 256, 64, batches);
    mma_gemm_k<<<grid, 256, GSMEM>>>(A, WH, bias, H2, C, K,
                                     lda, ldc, sAi, sBi, sCi, sBias, flags);
}

extern "C" void kernel_launch(void* const* d_in, const int* in_sizes, int n_in,
                              void* d_out, int out_size)
{
    const float* seg   = (const float*)d_in[0];
    const float* mask  = (const float*)d_in[1];
    const float* se    = (const float*)d_in[2];
    const float* hw1   = (const float*)d_in[3];
    const float* hb1   = (const float*)d_in[4];
    const float* hw2   = (const float*)d_in[5];
    const float* hb2   = (const float*)d_in[6];
    const float* hw3   = (const float*)d_in[7];
    const float* hb3   = (const float*)d_in[8];
    const float* lcW   = (const float*)d_in[9];
    const float* lcb   = (const float*)d_in[10];
    const float* lvW   = (const float*)d_in[11];
    const float* lvb   = (const float*)d_in[12];
    const float* gcW   = (const float*)d_in[13];
    const float* gcb   = (const float*)d_in[14];
    const float* gvW   = (const float*)d_in[15];
    const float* gvb   = (const float*)d_in[16];
    const float* sw1   = (const float*)d_in[17];
    const float* sw2   = (const float*)d_in[18];
    float* out = (float*)d_out;

    cudaFuncSetAttribute(mma_gemm_k,   cudaFuncAttributeMaxDynamicSharedMemorySize, GSMEM);
    cudaFuncSetAttribute(flash_k,      cudaFuncAttributeMaxDynamicSharedMemorySize, FSMEM);
    cudaFuncSetAttribute(local_attn_k, cudaFuncAttributeMaxDynamicSharedMemorySize, LSMEM);

    __half *pSeg, *pWH, *pB1, *pM, *pCT, *pA;
    float *pBias, *pH2;
    cudaGetSymbolAddress((void**)&pSeg, g_seg);
    cudaGetSymbolAddress((void**)&pWH, g_WH);
    cudaGetSymbolAddress((void**)&pB1, g_B1);
    cudaGetSymbolAddress((void**)&pM,  g_M);
    cudaGetSymbolAddress((void**)&pCT, g_CT);
    cudaGetSymbolAddress((void**)&pA,  g_A);
    cudaGetSymbolAddress((void**)&pBias, g_biasC);
    cudaGetSymbolAddress((void**)&pH2, g_H2);

    // merged prepass
    prep_all_k<<<1024, 256>>>(seg, hw1, hw3, lcW, lvW, gcW, gvW, lcb, lvb, gcb, gvb);

    // 1) h2
    h2_k<<<dim3(Bb * Nn, 4), dim3(128, 8)>>>(se, hw2, hb2);

    // 2) h1 = relu(seg @ w1 + b1) * h2
    mgemm(pSeg, pWH + OFF_HW1, hb1, pH2, pB1,
          512, 512, 512, 512, Nn, 0, 262144L, BLD, 512, 2 | 8);

    // 3) m = relu(h1m @ w3 + b3)
    mgemm(pB1, pWH + OFF_HW3, hb3, nullptr, pM,
          512, 512, 512, 512, Nn, BLD, 262144L, BLD, 512, 2);

    // 4) local NL: projection + band-pruned MMA attention
    for (int s = 0; s < 2; s++) {
        mgemm(pM, pWH + OFF_LCV + (long)s * 786432, pBias + s * 1536, nullptr, pCT,
              1536, 512, 512, 1536, Nn, BLD, 2L * 786432, CTN, 3072, 0);
        local_attn_k<<<dim3(4, Bb * Hh, Nn), 256, LSMEM>>>(mask);
    }

    // 5) segment attention weights
    satt_k<<<Bb, dim3(256, 4)>>>(se, sw1, sw2, out + BLD);

    // 6) aggregate
    agg_k<<<2048, 256>>>();

    // 7) global NL: projection + flash attention
    for (int s = 0; s < 2; s++) {
        mgemm(pA, pWH + OFF_GCV + (long)s * 786432, pBias + (6 + s) * 1536, nullptr, pCT,
              1536, 512, 512, 1536, 1, 0, 0, 0, 0, 0);
        flash_k<<<dim3(4, Bb * Hh), 256, FSMEM>>>(mask, (s == 1) ? out : nullptr);
    }
}

// round 16
// speedup vs baseline: 2.1223x; 2.1223x over previous
#include <cuda_runtime.h>
#include <cuda_fp16.h>
#include <math.h>
#include <stdint.h>

#define Bb 16
#define Ll 512
#define Dd 512
#define Nn 3
#define Hh 8
#define DH 64
#define AH 256
#define KHALF 7

#define BLD 4194304L        // Bb*Ll*Dd
#define CTN 12582912L       // 8192*1536 per n
#define CTSZ 37748736L      // 3 * CTN

// ---------------- scratch ------------------------------------------------------
__device__ __half g_seg[BLD];
__device__ __half g_WH[7864320];                  // fp16, tiled 32x128 blocks
__device__ __half g_B1[3*BLD];
__device__ __half g_M [3*BLD];
__device__ __half g_CT[CTSZ];                     // [n][8192][1536] mq|mv|mk
__device__ __half g_A [BLD];
__device__ float g_H2[Bb*Nn*Dd];
__device__ float g_SW[Bb*Nn];
__device__ float g_biasC[8*1536];

#define OFF_HW1 0L
#define OFF_HW3 786432L
#define OFF_LCV 1572864L
#define OFF_GCV 6291456L

// ---------------- PTX helpers --------------------------------------------------
__device__ __forceinline__ uint32_t smem_u32(const void* p) {
    uint32_t a;
    asm("{ .reg .u64 t; cvta.to.shared.u64 t, %1; cvt.u32.u64 %0, t; }" : "=r"(a) : "l"(p));
    return a;
}
#define CPA16(dst, src) asm volatile( \
    "cp.async.ca.shared.global [%0], [%1], 16;" :: "r"(dst), "l"(__cvta_generic_to_global(src)))
#define CPA_COMMIT() asm volatile("cp.async.commit_group;" ::: "memory")
#define CPA_WAIT1()  asm volatile("cp.async.wait_group 1;" ::: "memory")

#define BULK(dst, src, sz, mb) asm volatile( \
    "cp.async.bulk.shared::cta.global.mbarrier::complete_tx::bytes [%0], [%1], %2, [%3];" \
    :: "r"(dst), "l"(__cvta_generic_to_global(src)), "r"((uint32_t)(sz)), "r"(mb) : "memory")

#define MBAR_INIT(mb, c)   asm volatile("mbarrier.init.shared.b64 [%0], %1;" :: "r"(mb), "r"((uint32_t)(c)) : "memory")
#define MBAR_EXPECT(mb, tx) asm volatile("mbarrier.arrive.expect_tx.shared.b64 _, [%0], %1;" :: "r"(mb), "r"((uint32_t)(tx)) : "memory")
#define FENCE_ASYNC_SHARED() asm volatile("fence.proxy.async.shared::cta;" ::: "memory")
#define MBAR_WAIT(mb, ph) do { \
    uint32_t _m = (mb), _p = (ph), _d; \
    asm volatile("{\n\t.reg .pred p;\n\tmbarrier.try_wait.parity.acquire.cta.shared::cta.b64 p, [%1], %2;\n\tselp.b32 %0, 1, 0, p;\n\t}" \
        : "=r"(_d) : "r"(_m), "r"(_p) : "memory"); \
    if (!_d) { \
        asm volatile("{\n\t.reg .pred P1;\n\tWL_%=:\n\tmbarrier.try_wait.parity.acquire.cta.shared::cta.b64 P1, [%0], %1, 0x989680;\n\t@P1 bra.uni WD_%=;\n\tbra.uni WL_%=;\n\tWD_%=:\n\t}" \
            :: "r"(_m), "r"(_p) : "memory"); \
    } } while (0)

#define LDM_X4(r, a) asm volatile( \
    "ldmatrix.sync.aligned.m8n8.x4.shared.b16 {%0,%1,%2,%3}, [%4];" \
    : "=r"((r)[0]),"=r"((r)[1]),"=r"((r)[2]),"=r"((r)[3]) : "r"(a))
#define LDM_X4T(r, a) asm volatile( \
    "ldmatrix.sync.aligned.m8n8.x4.trans.shared.b16 {%0,%1,%2,%3}, [%4];" \
    : "=r"((r)[0]),"=r"((r)[1]),"=r"((r)[2]),"=r"((r)[3]) : "r"(a))
#define MMAF16(d, a, b) asm volatile( \
    "mma.sync.aligned.m16n8k16.row.col.f32.f16.f16.f32 " \
    "{%0,%1,%2,%3}, {%4,%5,%6,%7}, {%8,%9}, {%0,%1,%2,%3};" \
    : "+f"((d)[0]),"+f"((d)[1]),"+f"((d)[2]),"+f"((d)[3]) \
    : "r"((a)[0]),"r"((a)[1]),"r"((a)[2]),"r"((a)[3]), "r"((b)[0]),"r"((b)[1]))

__device__ __forceinline__ uint32_t packh2(float a, float b) {
    __half2 t = __floats2half2_rn(a, b);
    return *reinterpret_cast<uint32_t*>(&t);
}

// ---------------- merged prepass ------------------------------------------------
__global__ void prep_all_k(const float* __restrict__ seg,
                           const float* __restrict__ hw1, const float* __restrict__ hw3,
                           const float* __restrict__ lcW, const float* __restrict__ lvW,
                           const float* __restrict__ gcW, const float* __restrict__ gvW,
                           const float* __restrict__ lcb, const float* __restrict__ lvb,
                           const float* __restrict__ gcb, const float* __restrict__ gvb)
{
    long gstride = (long)gridDim.x * blockDim.x * 4;
    for (long i = ((long)blockIdx.x * blockDim.x + threadIdx.x) * 4; i < BLD; i += gstride) {
        float4 v = *reinterpret_cast<const float4*>(seg + i);
        uint2 o;
        o.x = packh2(v.x, v.y);
        o.y = packh2(v.z, v.w);
        *reinterpret_cast<uint2*>(g_seg + i) = o;
    }
    const float* srcs[6] = {hw1, hw3, lcW, lvW, gcW, gvW};
    const long  woff[6]  = {OFF_HW1, OFF_HW3, OFF_LCV, OFF_LCV, OFF_GCV, OFF_GCV};
    const int   C1s[6]   = {512, 512, 1024, 512, 1024, 512};
    const int   coff[6]  = {0, 0, 0, 1024, 0, 1024};
    const long  dss[6]   = {262144L, 262144L, 786432L, 786432L, 786432L, 786432L};
    const long  tots[6]  = {786432L, 786432L, 3145728L, 1572864L, 1048576L, 524288L};
    #pragma unroll 1
    for (int sg = 0; sg < 6; sg++) {
        const float* s = srcs[sg];
        int C1 = C1s[sg];
        long sS = 512L * C1;
        for (long i = ((long)blockIdx.x * blockDim.x + threadIdx.x) * 4; i < tots[sg];
             i += gstride) {
            float4 v = *reinterpret_cast<const float4*>(s + i);
            long sl = i / sS;
            long rem = i - sl * sS;
            int k = (int)(rem / C1), c = (int)(rem - (long)(rem / C1) * C1);
            int n = coff[sg] + c;
            long d = woff[sg] + sl * dss[sg] + ((long)((n >> 7) * 16 + (k >> 5))) * 4096
                   + (k & 31) * 128 + ((((n & 127) >> 3) ^ (k & 7)) << 3) + (n & 7);
            float vv[4] = {v.x, v.y, v.z, v.w};
            #pragma unroll
            for (int e = 0; e < 4; e++)
                g_WH[d + e] = __float2half_rn(vv[e]);
        }
    }
    for (long i = (long)blockIdx.x * blockDim.x + threadIdx.x; i < 8 * 1536;
         i += (long)gridDim.x * blockDim.x) {
        int slot = (int)(i / 1536), c = (int)(i % 1536);
        float v;
        if (slot < 6) v = (c < 1024) ? lcb[slot * 1024 + c] : lvb[slot * 512 + c - 1024];
        else {
            int s = slot - 6;
            v = (c < 1024) ? gcb[s * 1024 + c] : gvb[s * 512 + c - 1024];
        }
        g_biasC[slot * 1536 + c] = v;
    }
}

// ---------------- GEMM: fp16, BN=128, BK=64, 2-stage, 2 CTAs/SM ----------------
#define A_SUB 10240
#define A_BYTES 20480
#define STAGE 36864
#define GSMEM 73744
__global__ void __launch_bounds__(256, 2) mma_gemm_k(
    const __half* __restrict__ A, const __half* __restrict__ WH,
    const float* __restrict__ bias, const float* __restrict__ H2,
    __half* __restrict__ C,
    int K, int lda, int ldc,
    long sAi, long sBi, long sCi, long sBias, int flags)
{
    extern __shared__ char dsm[];
    uint32_t sb0 = smem_u32(dsm);
    uint32_t mbar0 = sb0 + 2 * STAGE;

    int z = blockIdx.z;
    A  += z * sAi;
    WH += z * sBi;
    C  += z * sCi;
    if (bias) bias += z * sBias;

    int tid = threadIdx.x, lane = tid & 31, wid = tid >> 5;
    int wm = wid & 1, wn = wid >> 1;        // wm: 2x64 rows, wn: 4x32 cols
    int m0 = blockIdx.y * 128;
    int bx = blockIdx.x, n0 = bx * 128;
    int nc = K / 64;
    int nk32 = K / 32;

    if (tid == 0) {
        MBAR_INIT(mbar0, 1); MBAR_INIT(mbar0 + 8, 1);
        FENCE_ASYNC_SHARED();
    }
    __syncthreads();

    auto fillA = [&](int c) {
        int k0 = c * 64;
        uint32_t st = sb0 + (c & 1) * STAGE;
        #pragma unroll
        for (int sub = 0; sub < 2; sub++) {
            #pragma unroll
            for (int it = 0; it < 2; it++) {
                int idx = tid + it * 256;
                int rr = idx >> 2, uu = idx & 3;
                CPA16(st + sub * A_SUB + rr * 80 + uu * 16,
                      A + (long)(m0 + rr) * lda + k0 + sub * 32 + uu * 8);
            }
        }
    };
    auto fillB = [&](int c) {
        uint32_t st = sb0 + (c & 1) * STAGE + A_BYTES;
        uint32_t mb = mbar0 + (c & 1) * 8;
        MBAR_EXPECT(mb, 16384u);
        long off = ((long)bx * nk32 + 2 * c) * 4096;
        BULK(st, WH + off, 16384, mb);
    };

    float acc[4][4][4] = {};

    fillA(0); CPA_COMMIT();
    fillA(1); CPA_COMMIT();
    if (tid == 0) { fillB(0); fillB(1); }

    int alr = lane & 15, alc = (lane >> 4) << 3;
    int btr = (lane & 7) + (((lane >> 3) & 1) << 3);
    int btcc = (lane >> 4) & 1;

    for (int c = 0; c < nc; c++) {
        CPA_WAIT1();
        MBAR_WAIT(mbar0 + (c & 1) * 8, (c >> 1) & 1);
        __syncthreads();

        uint32_t base = sb0 + (c & 1) * STAGE;

        #pragma unroll
        for (int kk = 0; kk < 4; kk++) {
            uint32_t ah[4][4], bh[4][2];
            uint32_t aA = base + (kk >> 1) * A_SUB +
                          (uint32_t)(((wm * 64 + alr) * 40 + (kk & 1) * 16 + alc) * 2);
            #pragma unroll
            for (int mt = 0; mt < 4; mt++)
                LDM_X4(ah[mt], aA + (uint32_t)(mt * 16 * 80));
            int krow = (kk & 1) * 16 + btr;
            uint32_t bB = base + A_BYTES + (kk >> 1) * 8192;
            #pragma unroll
            for (int p = 0; p < 2; p++) {
                int c16 = wn * 4 + p * 2 + btcc;
                uint32_t ad = bB + (uint32_t)(krow * 256 + ((c16 ^ (krow & 7)) << 4));
                uint32_t r[4];
                LDM_X4T(r, ad);
                bh[2*p][0]=r[0]; bh[2*p][1]=r[1]; bh[2*p+1][0]=r[2]; bh[2*p+1][1]=r[3];
            }
            #pragma unroll
            for (int mt = 0; mt < 4; mt++)
                #pragma unroll
                for (int nt = 0; nt < 4; nt++)
                    MMAF16(acc[mt][nt], ah[mt], bh[nt]);
        }

        __syncthreads();
        if (c + 2 < nc) {
            fillA(c + 2);
            CPA_COMMIT();
            if (tid == 0) fillB(c + 2);
        } else {
            CPA_COMMIT();
        }
    }

    const float* H2b = (flags & 8) ? (H2 + ((long)(m0 >> 9) * Nn + z) * 512) : nullptr;

    #pragma unroll
    for (int mt = 0; mt < 4; mt++) {
        int row = m0 + wm * 64 + mt * 16 + (lane >> 2);
        #pragma unroll
        for (int nt = 0; nt < 4; nt++) {
            int col = n0 + wn * 32 + nt * 8 + (lane & 3) * 2;
            float d0 = acc[mt][nt][0], d1 = acc[mt][nt][1];
            float d2 = acc[mt][nt][2], d3 = acc[mt][nt][3];
            if (bias) {
                float b0 = bias[col], b1 = bias[col + 1];
                d0 += b0; d1 += b1; d2 += b0; d3 += b1;
            }
            if (flags & 2) {
                d0 = fmaxf(d0, 0.f); d1 = fmaxf(d1, 0.f);
                d2 = fmaxf(d2, 0.f); d3 = fmaxf(d3, 0.f);
            }
            if (H2b) {
                float f0 = H2b[col], f1 = H2b[col + 1];
                d0 *= f0; d1 *= f1; d2 *= f0; d3 *= f1;
            }
            long o0 = (long)row * ldc + col;
            long o1 = o0 + (long)8 * ldc;
            *reinterpret_cast<uint32_t*>(C + o0) = packh2(d0, d1);
            *reinterpret_cast<uint32_t*>(C + o1) = packh2(d2, d3);
        }
    }
}

// ---------------- flash global attention ---------------------------------------
#define FQ 0
#define FK 18432
#define FV 36864
#define FMSK 55296
#define FSMEM 57344
#define FLDQ 72

__global__ void __launch_bounds__(256, 1) flash_k(const float* __restrict__ mask,
                                                  float* __restrict__ outp)
{
    extern __shared__ char sm[];
    uint32_t sb = smem_u32(sm);
    float* mbias = reinterpret_cast<float*>(sm + FMSK);
    int tid = threadIdx.x, lane = tid & 31, w = tid >> 5;
    int b = blockIdx.y >> 3, h = blockIdx.y & 7;
    int l0 = blockIdx.x * 128;
    long base = (long)b * 512 * 1536;

    for (int i = tid; i < 1024; i += 256) {
        int row = i >> 3, u = i & 7;
        *reinterpret_cast<uint4*>(sm + FQ + row * 144 + u * 16) =
            *reinterpret_cast<const uint4*>(g_CT + base + (long)(l0 + row) * 1536 + 1024 + h * DH + u * 8);
    }
    for (int i = tid; i < 512; i += 256)
        mbias[i] = (mask[(long)b * 512 + i] != 0.f) ? 0.f : -1e9f;

    float O[8][4];
    #pragma unroll
    for (int i = 0; i < 8; i++)
        #pragma unroll
        for (int e = 0; e < 4; e++) O[i][e] = 0.f;
    float mrow[2] = {-1e30f, -1e30f}, lrow[2] = {0.f, 0.f};

    int alr = lane & 15, alc = (lane >> 4) << 3;
    int blr = (lane & 7) + (((lane >> 4) & 1) << 3), blc = ((lane >> 3) & 1) << 3;
    int btr = (lane & 7) + (((lane >> 3) & 1) << 3), btc = ((lane >> 4) & 1) << 3;
    int c0 = (lane & 3) * 2;

    for (int mi = 0; mi < 4; mi++) {
        int m0 = mi * 128;
        __syncthreads();
        for (int i = tid; i < 1024; i += 256) {
            int row = i >> 3, u = i & 7;
            long gq = base + (long)(m0 + row) * 1536 + h * DH + u * 8;
            *reinterpret_cast<uint4*>(sm + FK + row * 144 + u * 16) =
                *reinterpret_cast<const uint4*>(g_CT + gq);
            *reinterpret_cast<uint4*>(sm + FV + row * 144 + u * 16) =
                *reinterpret_cast<const uint4*>(g_CT + gq + 512);
        }
        __syncthreads();

        float S[16][4];
        #pragma unroll
        for (int i = 0; i < 16; i++)
            #pragma unroll
            for (int e = 0; e < 4; e++) S[i][e] = 0.f;

        #pragma unroll
        for (int kc = 0; kc < 4; kc++) {
            uint32_t q[4];
            LDM_X4(q, sb + FQ + (uint32_t)(((w * 16 + alr) * FLDQ + kc * 16 + alc) * 2));
            #pragma unroll
            for (int p = 0; p < 8; p++) {
                uint32_t kf[4];
                LDM_X4(kf, sb + FK + (uint32_t)(((p * 16 + blr) * FLDQ + kc * 16 + blc) * 2));
                uint32_t b0[2] = {kf[0], kf[1]}, b1[2] = {kf[2], kf[3]};
                MMAF16(S[2*p],   q, b0);
                MMAF16(S[2*p+1], q, b1);
            }
        }

        float cmax[2] = {-1e30f, -1e30f};
        #pragma unroll
        for (int nt = 0; nt < 16; nt++)
            #pragma unroll
            for (int e = 0; e < 4; e++) {
                int col = m0 + nt * 8 + c0 + (e & 1);
                float v = S[nt][e] * 0.125f + mbias[col];
                S[nt][e] = v;
                cmax[e >> 1] = fmaxf(cmax[e >> 1], v);
            }
        #pragma unroll
        for (int o = 1; o <= 2; o <<= 1) {
            cmax[0] = fmaxf(cmax[0], __shfl_xor_sync(0xffffffffu, cmax[0], o));
            cmax[1] = fmaxf(cmax[1], __shfl_xor_sync(0xffffffffu, cmax[1], o));
        }
        float mn0 = fmaxf(mrow[0], cmax[0]), mn1 = fmaxf(mrow[1], cmax[1]);
        float a0 = __expf(mrow[0] - mn0), a1 = __expf(mrow[1] - mn1);
        mrow[0] = mn0; mrow[1] = mn1;
        lrow[0] *= a0; lrow[1] *= a1;
        #pragma unroll
        for (int i = 0; i < 8; i++) {
            O[i][0] *= a0; O[i][1] *= a0; O[i][2] *= a1; O[i][3] *= a1;
        }
        #pragma unroll
        for (int nt = 0; nt < 16; nt++)
            #pragma unroll
            for (int e = 0; e < 4; e++) {
                float p = __expf(S[nt][e] - ((e < 2) ? mn0 : mn1));
                S[nt][e] = p;
                lrow[e >> 1] += p;
            }

        #pragma unroll
        for (int kc = 0; kc < 8; kc++) {
            uint32_t ph[4];
            ph[0] = packh2(S[2*kc][0],   S[2*kc][1]);
            ph[1] = packh2(S[2*kc][2],   S[2*kc][3]);
            ph[2] = packh2(S[2*kc+1][0], S[2*kc+1][1]);
            ph[3] = packh2(S[2*kc+1][2], S[2*kc+1][3]);
            #pragma unroll
            for (int p = 0; p < 4; p++) {
                uint32_t vh[4];
                LDM_X4T(vh, sb + FV + (uint32_t)(((kc * 16 + btr) * FLDQ + p * 16 + btc) * 2));
                uint32_t b0[2] = {vh[0], vh[1]}, b1[2] = {vh[2], vh[3]};
                MMAF16(O[2*p],   ph, b0);
                MMAF16(O[2*p+1], ph, b1);
            }
        }
    }

    #pragma unroll
    for (int o = 1; o <= 2; o <<= 1) {
        lrow[0] += __shfl_xor_sync(0xffffffffu, lrow[0], o);
        lrow[1] += __shfl_xor_sync(0xffffffffu, lrow[1], o);
    }
    float inv0 = 1.f / lrow[0], inv1 = 1.f / lrow[1];

    int r0g = l0 + w * 16 + (lane >> 2);
    #pragma unroll
    for (int nt = 0; nt < 8; nt++) {
        int col = h * DH + nt * 8 + c0;
        long o0 = ((long)b * 512 + r0g) * 512 + col;
        long o1 = o0 + 8 * 512;
        __half2 x0 = *reinterpret_cast<const __half2*>(g_A + o0);
        __half2 x1 = *reinterpret_cast<const __half2*>(g_A + o1);
        float d0 = __low2float(x0) + O[nt][0] * inv0;
        float d1 = __high2float(x0) + O[nt][1] * inv0;
        float d2 = __low2float(x1) + O[nt][2] * inv1;
        float d3 = __high2float(x1) + O[nt][3] * inv1;
        if (outp) {
            *reinterpret_cast<float2*>(outp + o0) = make_float2(d0, d1);
            *reinterpret_cast<float2*>(outp + o1) = make_float2(d2, d3);
        } else {
            *reinterpret_cast<uint32_t*>(g_A + o0) = packh2(d0, d1);
            *reinterpret_cast<uint32_t*>(g_A + o1) = packh2(d2, d3);
        }
    }
}

// ---------------- MMA banded local attention (band-pruned) ----------------------
#define LK2 0
#define LMQ2 18432
#define LMV2 39168
#define LBI2 59904
#define LSMEM 60480

__global__ void __launch_bounds__(256, 1) local_attn_k(const float* __restrict__ mask)
{
    extern __shared__ char sm[];
    uint32_t sb = smem_u32(sm);
    float* sBias = reinterpret_cast<float*>(sm + LBI2);
    int tid = threadIdx.x, lane = tid & 31, w = tid >> 5;
    int b = blockIdx.y >> 3, h = blockIdx.y & 7;
    int n = blockIdx.z;
    int l0 = blockIdx.x * 128;
    long base = (long)n * CTN + (long)b * 512 * 1536;

    for (int i = tid; i < 1024; i += 256) {
        int row = i >> 3, u = i & 7;
        *reinterpret_cast<uint4*>(sm + LK2 + row * 144 + u * 16) =
            *reinterpret_cast<const uint4*>(g_CT + base + (long)(l0 + row) * 1536 + 1024 + h * DH + u * 8);
    }
    for (int i = tid; i < 1152; i += 256) {
        int r = i >> 3, u = i & 7;
        int m = l0 - 8 + r;
        if (m >= 0 && m < 512) {
            long g = base + (long)m * 1536 + h * DH + u * 8;
            *reinterpret_cast<uint4*>(sm + LMQ2 + r * 144 + u * 16) =
                *reinterpret_cast<const uint4*>(g_CT + g);
            *reinterpret_cast<uint4*>(sm + LMV2 + r * 144 + u * 16) =
                *reinterpret_cast<const uint4*>(g_CT + g + 512);
        } else {
            uint4 z = make_uint4(0, 0, 0, 0);
            *reinterpret_cast<uint4*>(sm + LMQ2 + r * 144 + u * 16) = z;
            *reinterpret_cast<uint4*>(sm + LMV2 + r * 144 + u * 16) = z;
        }
    }
    for (int i = tid; i < 144; i += 256) {
        int m = l0 - 8 + i;
        sBias[i] = (m >= 0 && m < 512 && mask[(long)b * 512 + m] != 0.f) ? 0.f : -1e9f;
    }
    __syncthreads();

    int alr = lane & 15, alc = (lane >> 4) << 3;
    int blr = (lane & 7) + (((lane >> 4) & 1) << 3), blc = ((lane >> 3) & 1) << 3;
    int btr = (lane & 7) + (((lane >> 3) & 1) << 3), btc = ((lane >> 4) & 1) << 3;
    int c0 = (lane & 3) * 2;
    int r0 = w * 16 + (lane >> 2);

    float S[4][4];
    #pragma unroll
    for (int i = 0; i < 4; i++)
        #pragma unroll
        for (int e = 0; e < 4; e++) S[i][e] = 0.f;

    #pragma unroll
    for (int kc = 0; kc < 4; kc++) {
        uint32_t aq[4];
        LDM_X4(aq, sb + LK2 + (uint32_t)(((w * 16 + alr) * 72 + kc * 16 + alc) * 2));
        #pragma unroll
        for (int pi = 0; pi < 2; pi++) {
            int p = w + pi;
            uint32_t kf[4];
            LDM_X4(kf, sb + LMQ2 + (uint32_t)(((p * 16 + blr) * 72 + kc * 16 + blc) * 2));
            uint32_t b0[2] = {kf[0], kf[1]}, b1[2] = {kf[2], kf[3]};
            MMAF16(S[2*pi],   aq, b0);
            MMAF16(S[2*pi+1], aq, b1);
        }
    }

    float mx0 = -1e30f, mx1 = -1e30f;
    #pragma unroll
    for (int i = 0; i < 4; i++)
        #pragma unroll
        for (int e = 0; e < 4; e++) {
            int col = (w + (i >> 1)) * 16 + (i & 1) * 8 + c0 + (e & 1);
            int lr = (e < 2) ? r0 : (r0 + 8);
            float v = S[i][e] * 0.125f + sBias[col];
            if (col < lr + 1 || col > lr + 15) v = -1e30f;
            S[i][e] = v;
            if (e < 2) mx0 = fmaxf(mx0, v); else mx1 = fmaxf(mx1, v);
        }
    #pragma unroll
    for (int o = 1; o <= 2; o <<= 1) {
        mx0 = fmaxf(mx0, __shfl_xor_sync(0xffffffffu, mx0, o));
        mx1 = fmaxf(mx1, __shfl_xor_sync(0xffffffffu, mx1, o));
    }
    float s0 = 0.f, s1 = 0.f;
    #pragma unroll
    for (int i = 0; i < 4; i++)
        #pragma unroll
        for (int e = 0; e < 4; e++) {
            float p = __expf(S[i][e] - ((e < 2) ? mx0 : mx1));
            S[i][e] = p;
            if (e < 2) s0 += p; else s1 += p;
        }
    #pragma unroll
    for (int o = 1; o <= 2; o <<= 1) {
        s0 += __shfl_xor_sync(0xffffffffu, s0, o);
        s1 += __shfl_xor_sync(0xffffffffu, s1, o);
    }
    float inv0 = 1.f / s0, inv1 = 1.f / s1;

    float O[8][4];
    #pragma unroll
    for (int i = 0; i < 8; i++)
        #pragma unroll
        for (int e = 0; e < 4; e++) O[i][e] = 0.f;

    #pragma unroll
    for (int ki = 0; ki < 2; ki++) {
        int kc = w + ki;
        uint32_t ph[4];
        ph[0] = packh2(S[2*ki][0],   S[2*ki][1]);
        ph[1] = packh2(S[2*ki][2],   S[2*ki][3]);
        ph[2] = packh2(S[2*ki+1][0], S[2*ki+1][1]);
        ph[3] = packh2(S[2*ki+1][2], S[2*ki+1][3]);
        #pragma unroll
        for (int p = 0; p < 4; p++) {
            uint32_t vh[4];
            LDM_X4T(vh, sb + LMV2 + (uint32_t)(((kc * 16 + btr) * 72 + p * 16 + btc) * 2));
            uint32_t b0[2] = {vh[0], vh[1]}, b1[2] = {vh[2], vh[3]};
            MMAF16(O[2*p],   ph, b0);
            MMAF16(O[2*p+1], ph, b1);
        }
    }

    int gl = l0 + r0;
    #pragma unroll
    for (int nt = 0; nt < 8; nt++) {
        int col = h * DH + nt * 8 + c0;
        long o0 = (long)n * BLD + ((long)b * 512 + gl) * 512 + col;
        long o1 = o0 + 8 * 512;
        __half2 x0 = *reinterpret_cast<const __half2*>(g_M + o0);
        __half2 x1 = *reinterpret_cast<const __half2*>(g_M + o1);
        *reinterpret_cast<uint32_t*>(g_M + o0) =
            packh2(__low2float(x0) + O[nt][0] * inv0, __high2float(x0) + O[nt][1] * inv0);
        *reinterpret_cast<uint32_t*>(g_M + o1) =
            packh2(__low2float(x1) + O[nt][2] * inv1, __high2float(x1) + O[nt][3] * inv1);
    }
}

// ---------------- small kernels ------------------------------------------------
__global__ void h2_k(const float* __restrict__ se, const float* __restrict__ w2,
                     const float* __restrict__ b2)
{
    __shared__ float red[8][128];
    int bn = blockIdx.x;
    int n = bn % Nn;
    int h = blockIdx.y * 128 + threadIdx.x;
    int ty = threadIdx.y;
    const float* x = se + (long)bn * Dd;
    const float* w = w2 + (long)n * Dd * Dd + h;
    int d0 = ty * 64;
    float a0 = 0.f, a1 = 0.f, a2 = 0.f, a3 = 0.f;
    #pragma unroll 4
    for (int d = d0; d < d0 + 64; d += 4) {
        a0 = fmaf(x[d],     w[(long)d * Dd],       a0);
        a1 = fmaf(x[d + 1], w[(long)(d + 1) * Dd], a1);
        a2 = fmaf(x[d + 2], w[(long)(d + 2) * Dd], a2);
        a3 = fmaf(x[d + 3], w[(long)(d + 3) * Dd], a3);
    }
    red[ty][threadIdx.x] = (a0 + a1) + (a2 + a3);
    __syncthreads();
    if (ty == 0) {
        float acc = b2[n * Dd + h];
        #pragma unroll
        for (int e = 0; e < 8; e++) acc += red[e][threadIdx.x];
        g_H2[(long)bn * Dd + h] = fmaxf(acc, 0.f);
    }
}

__global__ void satt_k(const float* __restrict__ se, const float* __restrict__ w1,
                       const float* __restrict__ w2, float* __restrict__ out_tail)
{
    __shared__ float red[4][256];
    __shared__ float s1[256];
    __shared__ float alpha[Nn];
    int b = blockIdx.x, t = threadIdx.x, y = threadIdx.y;
    for (int n = 0; n < Nn; n++) {
        const float* x = se + ((long)b * Nn + n) * Dd;
        int d0 = y * 128;
        float a0 = 0.f, a1 = 0.f, a2 = 0.f, a3 = 0.f;
        #pragma unroll 4
        for (int d = d0; d < d0 + 128; d += 4) {
            a0 = fmaf(x[d],     w1[(long)d * AH + t],       a0);
            a1 = fmaf(x[d + 1], w1[(long)(d + 1) * AH + t], a1);
            a2 = fmaf(x[d + 2], w1[(long)(d + 2) * AH + t], a2);
            a3 = fmaf(x[d + 3], w1[(long)(d + 3) * AH + t], a3);
        }
        red[y][t] = (a0 + a1) + (a2 + a3);
        __syncthreads();
        if (y == 0) {
            float dot = red[0][t] + red[1][t] + red[2][t] + red[3][t];
            s1[t] = tanhf(dot) * w2[t];
        }
        __syncthreads();
        for (int o = 128; o; o >>= 1) {
            if (y == 0 && t < o) s1[t] += s1[t + o];
            __syncthreads();
        }
        if (y == 0 && t == 0) alpha[n] = s1[0];
        __syncthreads();
    }
    if (y == 0 && t == 0) {
        float mx = fmaxf(alpha[0], fmaxf(alpha[1], alpha[2]));
        float e[Nn], sum = 0.f;
        for (int n = 0; n < Nn; n++) { e[n] = expf(alpha[n] - mx); sum += e[n]; }
        for (int n = 0; n < Nn; n++) {
            float w = e[n] / sum;
            g_SW[b * Nn + n] = w;
            out_tail[b * Nn + n] = w;
        }
    }
}

__global__ void agg_k()
{
    long half_total = BLD / 2;
    long stride = (long)Ll * Dd / 2;
    for (long i = (long)blockIdx.x * blockDim.x + threadIdx.x; i < half_total;
         i += (long)gridDim.x * blockDim.x) {
        int b = (int)(i / stride);
        float a0 = 0.f, a1 = 0.f;
        #pragma unroll
        for (int n = 0; n < Nn; n++) {
            float sw = g_SW[b * Nn + n];
            __half2 v = *reinterpret_cast<const __half2*>(g_M + (long)n * BLD + i * 2);
            a0 = fmaf(sw, __low2float(v), a0);
            a1 = fmaf(sw, __high2float(v), a1);
        }
        *reinterpret_cast<uint32_t*>(g_A + i * 2) = packh2(a0, a1);
    }
}

// ---------------- host orchestration ------------------------------------------
static void mgemm(const __half* A, const __half* WH,
                  const float* bias, const float* H2, __half* C,
                  int N, int K, int lda, int ldc, int batches,
                  long sAi, long sBi, long sCi, long sBias, int flags)
{
    dim3 grid(N / 128, 64, batches);
    mma_gemm_k<<<grid, 256, GSMEM>>>(A, WH, bias, H2, C, K,
                                     lda, ldc, sAi, sBi, sCi, sBias, flags);
}

extern "C" void kernel_launch(void* const* d_in, const int* in_sizes, int n_in,
                              void* d_out, int out_size)
{
    const float* seg   = (const float*)d_in[0];
    const float* mask  = (const float*)d_in[1];
    const float* se    = (const float*)d_in[2];
    const float* hw1   = (const float*)d_in[3];
    const float* hb1   = (const float*)d_in[4];
    const float* hw2   = (const float*)d_in[5];
    const float* hb2   = (const float*)d_in[6];
    const float* hw3   = (const float*)d_in[7];
    const float* hb3   = (const float*)d_in[8];
    const float* lcW   = (const float*)d_in[9];
    const float* lcb   = (const float*)d_in[10];
    const float* lvW   = (const float*)d_in[11];
    const float* lvb   = (const float*)d_in[12];
    const float* gcW   = (const float*)d_in[13];
    const float* gcb   = (const float*)d_in[14];
    const float* gvW   = (const float*)d_in[15];
    const float* gvb   = (const float*)d_in[16];
    const float* sw1   = (const float*)d_in[17];
    const float* sw2   = (const float*)d_in[18];
    float* out = (float*)d_out;

    cudaFuncSetAttribute(mma_gemm_k,   cudaFuncAttributeMaxDynamicSharedMemorySize, GSMEM);
    cudaFuncSetAttribute(flash_k,      cudaFuncAttributeMaxDynamicSharedMemorySize, FSMEM);
    cudaFuncSetAttribute(local_attn_k, cudaFuncAttributeMaxDynamicSharedMemorySize, LSMEM);

    __half *pSeg, *pWH, *pB1, *pM, *pCT, *pA;
    float *pBias, *pH2;
    cudaGetSymbolAddress((void**)&pSeg, g_seg);
    cudaGetSymbolAddress((void**)&pWH, g_WH);
    cudaGetSymbolAddress((void**)&pB1, g_B1);
    cudaGetSymbolAddress((void**)&pM,  g_M);
    cudaGetSymbolAddress((void**)&pCT, g_CT);
    cudaGetSymbolAddress((void**)&pA,  g_A);
    cudaGetSymbolAddress((void**)&pBias, g_biasC);
    cudaGetSymbolAddress((void**)&pH2, g_H2);

    // merged prepass
    prep_all_k<<<1024, 256>>>(seg, hw1, hw3, lcW, lvW, gcW, gvW, lcb, lvb, gcb, gvb);

    // 1) h2
    h2_k<<<dim3(Bb * Nn, 4), dim3(128, 8)>>>(se, hw2, hb2);

    // 2) h1 = relu(seg @ w1 + b1) * h2
    mgemm(pSeg, pWH + OFF_HW1, hb1, pH2, pB1,
          512, 512, 512, 512, Nn, 0, 262144L, BLD, 512, 2 | 8);

    // 3) m = relu(h1m @ w3 + b3)
    mgemm(pB1, pWH + OFF_HW3, hb3, nullptr, pM,
          512, 512, 512, 512, Nn, BLD, 262144L, BLD, 512, 2);

    // 4) local NL: projection + band-pruned MMA attention
    for (int s = 0; s < 2; s++) {
        mgemm(pM, pWH + OFF_LCV + (long)s * 786432, pBias + s * 1536, nullptr, pCT,
              1536, 512, 512, 1536, Nn, BLD, 2L * 786432, CTN, 3072, 0);
        local_attn_k<<<dim3(4, Bb * Hh, Nn), 256, LSMEM>>>(mask);
    }

    // 5) segment attention weights
    satt_k<<<Bb, dim3(256, 4)>>>(se, sw1, sw2, out + BLD);

    // 6) aggregate
    agg_k<<<2048, 256>>>();

    // 7) global NL: projection + flash attention
    for (int s = 0; s < 2; s++) {
        mgemm(pA, pWH + OFF_GCV + (long)s * 786432, pBias + (6 + s) * 1536, nullptr, pCT,
              1536, 512, 512, 1536, 1, 0, 0, 0, 0, 0);
        flash_k<<<dim3(4, Bb * Hh), 256, FSMEM>>>(mask, (s == 1) ? out : nullptr);
    }
}

// round 17
// speedup vs baseline: 2.1436x; 1.0100x over previous
#include <cuda_runtime.h>
#include <cuda_fp16.h>
#include <math.h>
#include <stdint.h>

#define Bb 16
#define Ll 512
#define Dd 512
#define Nn 3
#define Hh 8
#define DH 64
#define AH 256
#define KHALF 7

#define BLD 4194304L        // Bb*Ll*Dd
#define CTN 12582912L       // 8192*1536 per n
#define CTSZ 37748736L      // 3 * CTN

// ---------------- scratch ------------------------------------------------------
__device__ __half g_seg[BLD];
__device__ __half g_WH[7864320];                  // fp16, tiled 32x128 blocks
__device__ __half g_B1[3*BLD];
__device__ __half g_M [3*BLD];
__device__ __half g_CT[CTSZ];                     // [n][8192][1536] mq|mv|mk
__device__ __half g_A [BLD];
__device__ float g_H2[Bb*Nn*Dd];
__device__ float g_SW[Bb*Nn];
__device__ float g_biasC[8*1536];

#define OFF_HW1 0L
#define OFF_HW3 786432L
#define OFF_LCV 1572864L
#define OFF_GCV 6291456L

// ---------------- PTX helpers --------------------------------------------------
__device__ __forceinline__ uint32_t smem_u32(const void* p) {
    uint32_t a;
    asm("{ .reg .u64 t; cvta.to.shared.u64 t, %1; cvt.u32.u64 %0, t; }" : "=r"(a) : "l"(p));
    return a;
}
#define CPA16(dst, src) asm volatile( \
    "cp.async.ca.shared.global [%0], [%1], 16;" :: "r"(dst), "l"(__cvta_generic_to_global(src)))
#define CPA_COMMIT() asm volatile("cp.async.commit_group;" ::: "memory")
#define CPA_WAIT1()  asm volatile("cp.async.wait_group 1;" ::: "memory")

#define BULK(dst, src, sz, mb) asm volatile( \
    "cp.async.bulk.shared::cta.global.mbarrier::complete_tx::bytes [%0], [%1], %2, [%3];" \
    :: "r"(dst), "l"(__cvta_generic_to_global(src)), "r"((uint32_t)(sz)), "r"(mb) : "memory")

#define MBAR_INIT(mb, c)   asm volatile("mbarrier.init.shared.b64 [%0], %1;" :: "r"(mb), "r"((uint32_t)(c)) : "memory")
#define MBAR_EXPECT(mb, tx) asm volatile("mbarrier.arrive.expect_tx.shared.b64 _, [%0], %1;" :: "r"(mb), "r"((uint32_t)(tx)) : "memory")
#define FENCE_ASYNC_SHARED() asm volatile("fence.proxy.async.shared::cta;" ::: "memory")
#define MBAR_WAIT(mb, ph) do { \
    uint32_t _m = (mb), _p = (ph), _d; \
    asm volatile("{\n\t.reg .pred p;\n\tmbarrier.try_wait.parity.acquire.cta.shared::cta.b64 p, [%1], %2;\n\tselp.b32 %0, 1, 0, p;\n\t}" \
        : "=r"(_d) : "r"(_m), "r"(_p) : "memory"); \
    if (!_d) { \
        asm volatile("{\n\t.reg .pred P1;\n\tWL_%=:\n\tmbarrier.try_wait.parity.acquire.cta.shared::cta.b64 P1, [%0], %1, 0x989680;\n\t@P1 bra.uni WD_%=;\n\tbra.uni WL_%=;\n\tWD_%=:\n\t}" \
            :: "r"(_m), "r"(_p) : "memory"); \
    } } while (0)

#define LDM_X4(r, a) asm volatile( \
    "ldmatrix.sync.aligned.m8n8.x4.shared.b16 {%0,%1,%2,%3}, [%4];" \
    : "=r"((r)[0]),"=r"((r)[1]),"=r"((r)[2]),"=r"((r)[3]) : "r"(a))
#define LDM_X4T(r, a) asm volatile( \
    "ldmatrix.sync.aligned.m8n8.x4.trans.shared.b16 {%0,%1,%2,%3}, [%4];" \
    : "=r"((r)[0]),"=r"((r)[1]),"=r"((r)[2]),"=r"((r)[3]) : "r"(a))
#define MMAF16(d, a, b) asm volatile( \
    "mma.sync.aligned.m16n8k16.row.col.f32.f16.f16.f32 " \
    "{%0,%1,%2,%3}, {%4,%5,%6,%7}, {%8,%9}, {%0,%1,%2,%3};" \
    : "+f"((d)[0]),"+f"((d)[1]),"+f"((d)[2]),"+f"((d)[3]) \
    : "r"((a)[0]),"r"((a)[1]),"r"((a)[2]),"r"((a)[3]), "r"((b)[0]),"r"((b)[1]))

__device__ __forceinline__ uint32_t packh2(float a, float b) {
    __half2 t = __floats2half2_rn(a, b);
    return *reinterpret_cast<uint32_t*>(&t);
}

// ---------------- merged prepass ------------------------------------------------
__global__ void prep_all_k(const float* __restrict__ seg,
                           const float* __restrict__ hw1, const float* __restrict__ hw3,
                           const float* __restrict__ lcW, const float* __restrict__ lvW,
                           const float* __restrict__ gcW, const float* __restrict__ gvW,
                           const float* __restrict__ lcb, const float* __restrict__ lvb,
                           const float* __restrict__ gcb, const float* __restrict__ gvb)
{
    long gstride = (long)gridDim.x * blockDim.x * 4;
    for (long i = ((long)blockIdx.x * blockDim.x + threadIdx.x) * 4; i < BLD; i += gstride) {
        float4 v = *reinterpret_cast<const float4*>(seg + i);
        uint2 o;
        o.x = packh2(v.x, v.y);
        o.y = packh2(v.z, v.w);
        *reinterpret_cast<uint2*>(g_seg + i) = o;
    }
    const float* srcs[6] = {hw1, hw3, lcW, lvW, gcW, gvW};
    const long  woff[6]  = {OFF_HW1, OFF_HW3, OFF_LCV, OFF_LCV, OFF_GCV, OFF_GCV};
    const int   C1s[6]   = {512, 512, 1024, 512, 1024, 512};
    const int   coff[6]  = {0, 0, 0, 1024, 0, 1024};
    const long  dss[6]   = {262144L, 262144L, 786432L, 786432L, 786432L, 786432L};
    const long  tots[6]  = {786432L, 786432L, 3145728L, 1572864L, 1048576L, 524288L};
    #pragma unroll 1
    for (int sg = 0; sg < 6; sg++) {
        const float* s = srcs[sg];
        int C1 = C1s[sg];
        long sS = 512L * C1;
        for (long i = ((long)blockIdx.x * blockDim.x + threadIdx.x) * 4; i < tots[sg];
             i += gstride) {
            float4 v = *reinterpret_cast<const float4*>(s + i);
            long sl = i / sS;
            long rem = i - sl * sS;
            int k = (int)(rem / C1), c = (int)(rem - (long)(rem / C1) * C1);
            int n = coff[sg] + c;
            long d = woff[sg] + sl * dss[sg] + ((long)((n >> 7) * 16 + (k >> 5))) * 4096
                   + (k & 31) * 128 + ((((n & 127) >> 3) ^ (k & 7)) << 3) + (n & 7);
            float vv[4] = {v.x, v.y, v.z, v.w};
            #pragma unroll
            for (int e = 0; e < 4; e++)
                g_WH[d + e] = __float2half_rn(vv[e]);
        }
    }
    for (long i = (long)blockIdx.x * blockDim.x + threadIdx.x; i < 8 * 1536;
         i += (long)gridDim.x * blockDim.x) {
        int slot = (int)(i / 1536), c = (int)(i % 1536);
        float v;
        if (slot < 6) v = (c < 1024) ? lcb[slot * 1024 + c] : lvb[slot * 512 + c - 1024];
        else {
            int s = slot - 6;
            v = (c < 1024) ? gcb[s * 1024 + c] : gvb[s * 512 + c - 1024];
        }
        g_biasC[slot * 1536 + c] = v;
    }
}

// ---------------- GEMM: fp16, BN=128, BK=64, 3-stage, 2 CTAs/SM ----------------
#define A_SUB 10240
#define A_BYTES 20480
#define STAGE 36864
#define GSMEM 110616
__global__ void __launch_bounds__(256, 2) mma_gemm_k(
    const __half* __restrict__ A, const __half* __restrict__ WH,
    const float* __restrict__ bias, const float* __restrict__ H2,
    __half* __restrict__ C,
    int K, int lda, int ldc,
    long sAi, long sBi, long sCi, long sBias, int flags)
{
    extern __shared__ char dsm[];
    uint32_t sb0 = smem_u32(dsm);
    uint32_t mbar0 = sb0 + 3 * STAGE;

    int z = blockIdx.z;
    A  += z * sAi;
    WH += z * sBi;
    C  += z * sCi;
    if (bias) bias += z * sBias;

    int tid = threadIdx.x, lane = tid & 31, wid = tid >> 5;
    int wm = wid & 1, wn = wid >> 1;        // wm: 2x64 rows, wn: 4x32 cols
    int m0 = blockIdx.y * 128;
    int bx = blockIdx.x, n0 = bx * 128;
    int nc = K / 64;
    int nk32 = K / 32;

    if (tid == 0) {
        MBAR_INIT(mbar0, 1); MBAR_INIT(mbar0 + 8, 1); MBAR_INIT(mbar0 + 16, 1);
        FENCE_ASYNC_SHARED();
    }
    __syncthreads();

    auto fillA = [&](int c) {
        int k0 = c * 64;
        uint32_t st = sb0 + (c % 3) * STAGE;
        #pragma unroll
        for (int sub = 0; sub < 2; sub++) {
            #pragma unroll
            for (int it = 0; it < 2; it++) {
                int idx = tid + it * 256;
                int rr = idx >> 2, uu = idx & 3;
                CPA16(st + sub * A_SUB + rr * 80 + uu * 16,
                      A + (long)(m0 + rr) * lda + k0 + sub * 32 + uu * 8);
            }
        }
    };
    auto fillB = [&](int c) {
        uint32_t st = sb0 + (c % 3) * STAGE + A_BYTES;
        uint32_t mb = mbar0 + (c % 3) * 8;
        MBAR_EXPECT(mb, 16384u);
        long off = ((long)bx * nk32 + 2 * c) * 4096;
        BULK(st, WH + off, 16384, mb);
    };

    float acc[4][4][4] = {};

    fillA(0); CPA_COMMIT();
    fillA(1); CPA_COMMIT();
    if (tid == 0) { fillB(0); fillB(1); }

    int alr = lane & 15, alc = (lane >> 4) << 3;
    int btr = (lane & 7) + (((lane >> 3) & 1) << 3);
    int btcc = (lane >> 4) & 1;

    for (int c = 0; c < nc; c++) {
        CPA_WAIT1();
        MBAR_WAIT(mbar0 + (c % 3) * 8, (c / 3) & 1);
        __syncthreads();
        if (c + 2 < nc) { fillA(c + 2); if (tid == 0) fillB(c + 2); }
        CPA_COMMIT();

        uint32_t base = sb0 + (c % 3) * STAGE;

        #pragma unroll
        for (int kk = 0; kk < 4; kk++) {
            uint32_t ah[4][4], bh[4][2];
            uint32_t aA = base + (kk >> 1) * A_SUB +
                          (uint32_t)(((wm * 64 + alr) * 40 + (kk & 1) * 16 + alc) * 2);
            #pragma unroll
            for (int mt = 0; mt < 4; mt++)
                LDM_X4(ah[mt], aA + (uint32_t)(mt * 16 * 80));
            int krow = (kk & 1) * 16 + btr;
            uint32_t bB = base + A_BYTES + (kk >> 1) * 8192;
            #pragma unroll
            for (int p = 0; p < 2; p++) {
                int c16 = wn * 4 + p * 2 + btcc;
                uint32_t ad = bB + (uint32_t)(krow * 256 + ((c16 ^ (krow & 7)) << 4));
                uint32_t r[4];
                LDM_X4T(r, ad);
                bh[2*p][0]=r[0]; bh[2*p][1]=r[1]; bh[2*p+1][0]=r[2]; bh[2*p+1][1]=r[3];
            }
            #pragma unroll
            for (int mt = 0; mt < 4; mt++)
                #pragma unroll
                for (int nt = 0; nt < 4; nt++)
                    MMAF16(acc[mt][nt], ah[mt], bh[nt]);
        }
    }

    const float* H2b = (flags & 8) ? (H2 + ((long)(m0 >> 9) * Nn + z) * 512) : nullptr;

    #pragma unroll
    for (int mt = 0; mt < 4; mt++) {
        int row = m0 + wm * 64 + mt * 16 + (lane >> 2);
        #pragma unroll
        for (int nt = 0; nt < 4; nt++) {
            int col = n0 + wn * 32 + nt * 8 + (lane & 3) * 2;
            float d0 = acc[mt][nt][0], d1 = acc[mt][nt][1];
            float d2 = acc[mt][nt][2], d3 = acc[mt][nt][3];
            if (bias) {
                float b0 = bias[col], b1 = bias[col + 1];
                d0 += b0; d1 += b1; d2 += b0; d3 += b1;
            }
            if (flags & 2) {
                d0 = fmaxf(d0, 0.f); d1 = fmaxf(d1, 0.f);
                d2 = fmaxf(d2, 0.f); d3 = fmaxf(d3, 0.f);
            }
            if (H2b) {
                float f0 = H2b[col], f1 = H2b[col + 1];
                d0 *= f0; d1 *= f1; d2 *= f0; d3 *= f1;
            }
            long o0 = (long)row * ldc + col;
            long o1 = o0 + (long)8 * ldc;
            *reinterpret_cast<uint32_t*>(C + o0) = packh2(d0, d1);
            *reinterpret_cast<uint32_t*>(C + o1) = packh2(d2, d3);
        }
    }
}

// ---------------- flash global attention ---------------------------------------
#define FQ 0
#define FK 18432
#define FV 36864
#define FMSK 55296
#define FSMEM 57344
#define FLDQ 72

__global__ void __launch_bounds__(256, 1) flash_k(const float* __restrict__ mask,
                                                  float* __restrict__ outp)
{
    extern __shared__ char sm[];
    uint32_t sb = smem_u32(sm);
    float* mbias = reinterpret_cast<float*>(sm + FMSK);
    int tid = threadIdx.x, lane = tid & 31, w = tid >> 5;
    int b = blockIdx.y >> 3, h = blockIdx.y & 7;
    int l0 = blockIdx.x * 128;
    long base = (long)b * 512 * 1536;

    for (int i = tid; i < 1024; i += 256) {
        int row = i >> 3, u = i & 7;
        *reinterpret_cast<uint4*>(sm + FQ + row * 144 + u * 16) =
            *reinterpret_cast<const uint4*>(g_CT + base + (long)(l0 + row) * 1536 + 1024 + h * DH + u * 8);
    }
    for (int i = tid; i < 512; i += 256)
        mbias[i] = (mask[(long)b * 512 + i] != 0.f) ? 0.f : -1e9f;

    float O[8][4];
    #pragma unroll
    for (int i = 0; i < 8; i++)
        #pragma unroll
        for (int e = 0; e < 4; e++) O[i][e] = 0.f;
    float mrow[2] = {-1e30f, -1e30f}, lrow[2] = {0.f, 0.f};

    int alr = lane & 15, alc = (lane >> 4) << 3;
    int blr = (lane & 7) + (((lane >> 4) & 1) << 3), blc = ((lane >> 3) & 1) << 3;
    int btr = (lane & 7) + (((lane >> 3) & 1) << 3), btc = ((lane >> 4) & 1) << 3;
    int c0 = (lane & 3) * 2;

    for (int mi = 0; mi < 4; mi++) {
        int m0 = mi * 128;
        __syncthreads();
        for (int i = tid; i < 1024; i += 256) {
            int row = i >> 3, u = i & 7;
            long gq = base + (long)(m0 + row) * 1536 + h * DH + u * 8;
            *reinterpret_cast<uint4*>(sm + FK + row * 144 + u * 16) =
                *reinterpret_cast<const uint4*>(g_CT + gq);
            *reinterpret_cast<uint4*>(sm + FV + row * 144 + u * 16) =
                *reinterpret_cast<const uint4*>(g_CT + gq + 512);
        }
        __syncthreads();

        float S[16][4];
        #pragma unroll
        for (int i = 0; i < 16; i++)
            #pragma unroll
            for (int e = 0; e < 4; e++) S[i][e] = 0.f;

        #pragma unroll
        for (int kc = 0; kc < 4; kc++) {
            uint32_t q[4];
            LDM_X4(q, sb + FQ + (uint32_t)(((w * 16 + alr) * FLDQ + kc * 16 + alc) * 2));
            #pragma unroll
            for (int p = 0; p < 8; p++) {
                uint32_t kf[4];
                LDM_X4(kf, sb + FK + (uint32_t)(((p * 16 + blr) * FLDQ + kc * 16 + blc) * 2));
                uint32_t b0[2] = {kf[0], kf[1]}, b1[2] = {kf[2], kf[3]};
                MMAF16(S[2*p],   q, b0);
                MMAF16(S[2*p+1], q, b1);
            }
        }

        float cmax[2] = {-1e30f, -1e30f};
        #pragma unroll
        for (int nt = 0; nt < 16; nt++)
            #pragma unroll
            for (int e = 0; e < 4; e++) {
                int col = m0 + nt * 8 + c0 + (e & 1);
                float v = S[nt][e] * 0.125f + mbias[col];
                S[nt][e] = v;
                cmax[e >> 1] = fmaxf(cmax[e >> 1], v);
            }
        #pragma unroll
        for (int o = 1; o <= 2; o <<= 1) {
            cmax[0] = fmaxf(cmax[0], __shfl_xor_sync(0xffffffffu, cmax[0], o));
            cmax[1] = fmaxf(cmax[1], __shfl_xor_sync(0xffffffffu, cmax[1], o));
        }
        float mn0 = fmaxf(mrow[0], cmax[0]), mn1 = fmaxf(mrow[1], cmax[1]);
        float a0 = __expf(mrow[0] - mn0), a1 = __expf(mrow[1] - mn1);
        mrow[0] = mn0; mrow[1] = mn1;
        lrow[0] *= a0; lrow[1] *= a1;
        #pragma unroll
        for (int i = 0; i < 8; i++) {
            O[i][0] *= a0; O[i][1] *= a0; O[i][2] *= a1; O[i][3] *= a1;
        }
        #pragma unroll
        for (int nt = 0; nt < 16; nt++)
            #pragma unroll
            for (int e = 0; e < 4; e++) {
                float p = __expf(S[nt][e] - ((e < 2) ? mn0 : mn1));
                S[nt][e] = p;
                lrow[e >> 1] += p;
            }

        #pragma unroll
        for (int kc = 0; kc < 8; kc++) {
            uint32_t ph[4];
            ph[0] = packh2(S[2*kc][0],   S[2*kc][1]);
            ph[1] = packh2(S[2*kc][2],   S[2*kc][3]);
            ph[2] = packh2(S[2*kc+1][0], S[2*kc+1][1]);
            ph[3] = packh2(S[2*kc+1][2], S[2*kc+1][3]);
            #pragma unroll
            for (int p = 0; p < 4; p++) {
                uint32_t vh[4];
                LDM_X4T(vh, sb + FV + (uint32_t)(((kc * 16 + btr) * FLDQ + p * 16 + btc) * 2));
                uint32_t b0[2] = {vh[0], vh[1]}, b1[2] = {vh[2], vh[3]};
                MMAF16(O[2*p],   ph, b0);
                MMAF16(O[2*p+1], ph, b1);
            }
        }
    }

    #pragma unroll
    for (int o = 1; o <= 2; o <<= 1) {
        lrow[0] += __shfl_xor_sync(0xffffffffu, lrow[0], o);
        lrow[1] += __shfl_xor_sync(0xffffffffu, lrow[1], o);
    }
    float inv0 = 1.f / lrow[0], inv1 = 1.f / lrow[1];

    int r0g = l0 + w * 16 + (lane >> 2);
    #pragma unroll
    for (int nt = 0; nt < 8; nt++) {
        int col = h * DH + nt * 8 + c0;
        long o0 = ((long)b * 512 + r0g) * 512 + col;
        long o1 = o0 + 8 * 512;
        __half2 x0 = *reinterpret_cast<const __half2*>(g_A + o0);
        __half2 x1 = *reinterpret_cast<const __half2*>(g_A + o1);
        float d0 = __low2float(x0) + O[nt][0] * inv0;
        float d1 = __high2float(x0) + O[nt][1] * inv0;
        float d2 = __low2float(x1) + O[nt][2] * inv1;
        float d3 = __high2float(x1) + O[nt][3] * inv1;
        if (outp) {
            *reinterpret_cast<float2*>(outp + o0) = make_float2(d0, d1);
            *reinterpret_cast<float2*>(outp + o1) = make_float2(d2, d3);
        } else {
            *reinterpret_cast<uint32_t*>(g_A + o0) = packh2(d0, d1);
            *reinterpret_cast<uint32_t*>(g_A + o1) = packh2(d2, d3);
        }
    }
}

// ---------------- MMA banded local attention (band-pruned) ----------------------
#define LK2 0
#define LMQ2 18432
#define LMV2 39168
#define LBI2 59904
#define LSMEM 60480

__global__ void __launch_bounds__(256, 1) local_attn_k(const float* __restrict__ mask)
{
    extern __shared__ char sm[];
    uint32_t sb = smem_u32(sm);
    float* sBias = reinterpret_cast<float*>(sm + LBI2);
    int tid = threadIdx.x, lane = tid & 31, w = tid >> 5;
    int b = blockIdx.y >> 3, h = blockIdx.y & 7;
    int n = blockIdx.z;
    int l0 = blockIdx.x * 128;
    long base = (long)n * CTN + (long)b * 512 * 1536;

    for (int i = tid; i < 1024; i += 256) {
        int row = i >> 3, u = i & 7;
        *reinterpret_cast<uint4*>(sm + LK2 + row * 144 + u * 16) =
            *reinterpret_cast<const uint4*>(g_CT + base + (long)(l0 + row) * 1536 + 1024 + h * DH + u * 8);
    }
    for (int i = tid; i < 1152; i += 256) {
        int r = i >> 3, u = i & 7;
        int m = l0 - 8 + r;
        if (m >= 0 && m < 512) {
            long g = base + (long)m * 1536 + h * DH + u * 8;
            *reinterpret_cast<uint4*>(sm + LMQ2 + r * 144 + u * 16) =
                *reinterpret_cast<const uint4*>(g_CT + g);
            *reinterpret_cast<uint4*>(sm + LMV2 + r * 144 + u * 16) =
                *reinterpret_cast<const uint4*>(g_CT + g + 512);
        } else {
            uint4 z = make_uint4(0, 0, 0, 0);
            *reinterpret_cast<uint4*>(sm + LMQ2 + r * 144 + u * 16) = z;
            *reinterpret_cast<uint4*>(sm + LMV2 + r * 144 + u * 16) = z;
        }
    }
    for (int i = tid; i < 144; i += 256) {
        int m = l0 - 8 + i;
        sBias[i] = (m >= 0 && m < 512 && mask[(long)b * 512 + m] != 0.f) ? 0.f : -1e9f;
    }
    __syncthreads();

    int alr = lane & 15, alc = (lane >> 4) << 3;
    int blr = (lane & 7) + (((lane >> 4) & 1) << 3), blc = ((lane >> 3) & 1) << 3;
    int btr = (lane & 7) + (((lane >> 3) & 1) << 3), btc = ((lane >> 4) & 1) << 3;
    int c0 = (lane & 3) * 2;
    int r0 = w * 16 + (lane >> 2);

    float S[4][4];
    #pragma unroll
    for (int i = 0; i < 4; i++)
        #pragma unroll
        for (int e = 0; e < 4; e++) S[i][e] = 0.f;

    #pragma unroll
    for (int kc = 0; kc < 4; kc++) {
        uint32_t aq[4];
        LDM_X4(aq, sb + LK2 + (uint32_t)(((w * 16 + alr) * 72 + kc * 16 + alc) * 2));
        #pragma unroll
        for (int pi = 0; pi < 2; pi++) {
            int p = w + pi;
            uint32_t kf[4];
            LDM_X4(kf, sb + LMQ2 + (uint32_t)(((p * 16 + blr) * 72 + kc * 16 + blc) * 2));
            uint32_t b0[2] = {kf[0], kf[1]}, b1[2] = {kf[2], kf[3]};
            MMAF16(S[2*pi],   aq, b0);
            MMAF16(S[2*pi+1], aq, b1);
        }
    }

    float mx0 = -1e30f, mx1 = -1e30f;
    #pragma unroll
    for (int i = 0; i < 4; i++)
        #pragma unroll
        for (int e = 0; e < 4; e++) {
            int col = (w + (i >> 1)) * 16 + (i & 1) * 8 + c0 + (e & 1);
            int lr = (e < 2) ? r0 : (r0 + 8);
            float v = S[i][e] * 0.125f + sBias[col];
            if (col < lr + 1 || col > lr + 15) v = -1e30f;
            S[i][e] = v;
            if (e < 2) mx0 = fmaxf(mx0, v); else mx1 = fmaxf(mx1, v);
        }
    #pragma unroll
    for (int o = 1; o <= 2; o <<= 1) {
        mx0 = fmaxf(mx0, __shfl_xor_sync(0xffffffffu, mx0, o));
        mx1 = fmaxf(mx1, __shfl_xor_sync(0xffffffffu, mx1, o));
    }
    float s0 = 0.f, s1 = 0.f;
    #pragma unroll
    for (int i = 0; i < 4; i++)
        #pragma unroll
        for (int e = 0; e < 4; e++) {
            float p = __expf(S[i][e] - ((e < 2) ? mx0 : mx1));
            S[i][e] = p;
            if (e < 2) s0 += p; else s1 += p;
        }
    #pragma unroll
    for (int o = 1; o <= 2; o <<= 1) {
        s0 += __shfl_xor_sync(0xffffffffu, s0, o);
        s1 += __shfl_xor_sync(0xffffffffu, s1, o);
    }
    float inv0 = 1.f / s0, inv1 = 1.f / s1;

    float O[8][4];
    #pragma unroll
    for (int i = 0; i < 8; i++)
        #pragma unroll
        for (int e = 0; e < 4; e++) O[i][e] = 0.f;

    #pragma unroll
    for (int ki = 0; ki < 2; ki++) {
        int kc = w + ki;
        uint32_t ph[4];
        ph[0] = packh2(S[2*ki][0],   S[2*ki][1]);
        ph[1] = packh2(S[2*ki][2],   S[2*ki][3]);
        ph[2] = packh2(S[2*ki+1][0], S[2*ki+1][1]);
        ph[3] = packh2(S[2*ki+1][2], S[2*ki+1][3]);
        #pragma unroll
        for (int p = 0; p < 4; p++) {
            uint32_t vh[4];
            LDM_X4T(vh, sb + LMV2 + (uint32_t)(((kc * 16 + btr) * 72 + p * 16 + btc) * 2));
            uint32_t b0[2] = {vh[0], vh[1]}, b1[2] = {vh[2], vh[3]};
            MMAF16(O[2*p],   ph, b0);
            MMAF16(O[2*p+1], ph, b1);
        }
    }

    int gl = l0 + r0;
    #pragma unroll
    for (int nt = 0; nt < 8; nt++) {
        int col = h * DH + nt * 8 + c0;
        long o0 = (long)n * BLD + ((long)b * 512 + gl) * 512 + col;
        long o1 = o0 + 8 * 512;
        __half2 x0 = *reinterpret_cast<const __half2*>(g_M + o0);
        __half2 x1 = *reinterpret_cast<const __half2*>(g_M + o1);
        *reinterpret_cast<uint32_t*>(g_M + o0) =
            packh2(__low2float(x0) + O[nt][0] * inv0, __high2float(x0) + O[nt][1] * inv0);
        *reinterpret_cast<uint32_t*>(g_M + o1) =
            packh2(__low2float(x1) + O[nt][2] * inv1, __high2float(x1) + O[nt][3] * inv1);
    }
}

// ---------------- small kernels ------------------------------------------------
__global__ void h2_k(const float* __restrict__ se, const float* __restrict__ w2,
                     const float* __restrict__ b2)
{
    __shared__ float red[8][128];
    int bn = blockIdx.x;
    int n = bn % Nn;
    int h = blockIdx.y * 128 + threadIdx.x;
    int ty = threadIdx.y;
    const float* x = se + (long)bn * Dd;
    const float* w = w2 + (long)n * Dd * Dd + h;
    int d0 = ty * 64;
    float a0 = 0.f, a1 = 0.f, a2 = 0.f, a3 = 0.f;
    #pragma unroll 4
    for (int d = d0; d < d0 + 64; d += 4) {
        a0 = fmaf(x[d],     w[(long)d * Dd],       a0);
        a1 = fmaf(x[d + 1], w[(long)(d + 1) * Dd], a1);
        a2 = fmaf(x[d + 2], w[(long)(d + 2) * Dd], a2);
        a3 = fmaf(x[d + 3], w[(long)(d + 3) * Dd], a3);
    }
    red[ty][threadIdx.x] = (a0 + a1) + (a2 + a3);
    __syncthreads();
    if (ty == 0) {
        float acc = b2[n * Dd + h];
        #pragma unroll
        for (int e = 0; e < 8; e++) acc += red[e][threadIdx.x];
        g_H2[(long)bn * Dd + h] = fmaxf(acc, 0.f);
    }
}

__global__ void satt_k(const float* __restrict__ se, const float* __restrict__ w1,
                       const float* __restrict__ w2, float* __restrict__ out_tail)
{
    __shared__ float red[4][256];
    __shared__ float s1[256];
    __shared__ float alpha[Nn];
    int b = blockIdx.x, t = threadIdx.x, y = threadIdx.y;
    for (int n = 0; n < Nn; n++) {
        const float* x = se + ((long)b * Nn + n) * Dd;
        int d0 = y * 128;
        float a0 = 0.f, a1 = 0.f, a2 = 0.f, a3 = 0.f;
        #pragma unroll 4
        for (int d = d0; d < d0 + 128; d += 4) {
            a0 = fmaf(x[d],     w1[(long)d * AH + t],       a0);
            a1 = fmaf(x[d + 1], w1[(long)(d + 1) * AH + t], a1);
            a2 = fmaf(x[d + 2], w1[(long)(d + 2) * AH + t], a2);
            a3 = fmaf(x[d + 3], w1[(long)(d + 3) * AH + t], a3);
        }
        red[y][t] = (a0 + a1) + (a2 + a3);
        __syncthreads();
        if (y == 0) {
            float dot = red[0][t] + red[1][t] + red[2][t] + red[3][t];
            s1[t] = tanhf(dot) * w2[t];
        }
        __syncthreads();
        for (int o = 128; o; o >>= 1) {
            if (y == 0 && t < o) s1[t] += s1[t + o];
            __syncthreads();
        }
        if (y == 0 && t == 0) alpha[n] = s1[0];
        __syncthreads();
    }
    if (y == 0 && t == 0) {
        float mx = fmaxf(alpha[0], fmaxf(alpha[1], alpha[2]));
        float e[Nn], sum = 0.f;
        for (int n = 0; n < Nn; n++) { e[n] = expf(alpha[n] - mx); sum += e[n]; }
        for (int n = 0; n < Nn; n++) {
            float w = e[n] / sum;
            g_SW[b * Nn + n] = w;
            out_tail[b * Nn + n] = w;
        }
    }
}

__global__ void agg_k()
{
    long half_total = BLD / 2;
    long stride = (long)Ll * Dd / 2;
    for (long i = (long)blockIdx.x * blockDim.x + threadIdx.x; i < half_total;
         i += (long)gridDim.x * blockDim.x) {
        int b = (int)(i / stride);
        float a0 = 0.f, a1 = 0.f;
        #pragma unroll
        for (int n = 0; n < Nn; n++) {
            float sw = g_SW[b * Nn + n];
            __half2 v = *reinterpret_cast<const __half2*>(g_M + (long)n * BLD + i * 2);
            a0 = fmaf(sw, __low2float(v), a0);
            a1 = fmaf(sw, __high2float(v), a1);
        }
        *reinterpret_cast<uint32_t*>(g_A + i * 2) = packh2(a0, a1);
    }
}

// ---------------- host orchestration ------------------------------------------
static void mgemm(const __half* A, const __half* WH,
                  const float* bias, const float* H2, __half* C,
                  int N, int K, int lda, int ldc, int batches,
                  long sAi, long sBi, long sCi, long sBias, int flags)
{
    dim3 grid(N / 128, 64, batches);
    mma_gemm_k<<<grid, 256, GSMEM>>>(A, WH, bias, H2, C, K,
                                     lda, ldc, sAi, sBi, sCi, sBias, flags);
}

extern "C" void kernel_launch(void* const* d_in, const int* in_sizes, int n_in,
                              void* d_out, int out_size)
{
    const float* seg   = (const float*)d_in[0];
    const float* mask  = (const float*)d_in[1];
    const float* se    = (const float*)d_in[2];
    const float* hw1   = (const float*)d_in[3];
    const float* hb1   = (const float*)d_in[4];
    const float* hw2   = (const float*)d_in[5];
    const float* hb2   = (const float*)d_in[6];
    const float* hw3   = (const float*)d_in[7];
    const float* hb3   = (const float*)d_in[8];
    const float* lcW   = (const float*)d_in[9];
    const float* lcb   = (const float*)d_in[10];
    const float* lvW   = (const float*)d_in[11];
    const float* lvb   = (const float*)d_in[12];
    const float* gcW   = (const float*)d_in[13];
    const float* gcb   = (const float*)d_in[14];
    const float* gvW   = (const float*)d_in[15];
    const float* gvb   = (const float*)d_in[16];
    const float* sw1   = (const float*)d_in[17];
    const float* sw2   = (const float*)d_in[18];
    float* out = (float*)d_out;

    cudaFuncSetAttribute(mma_gemm_k,   cudaFuncAttributeMaxDynamicSharedMemorySize, GSMEM);
    cudaFuncSetAttribute(flash_k,      cudaFuncAttributeMaxDynamicSharedMemorySize, FSMEM);
    cudaFuncSetAttribute(local_attn_k, cudaFuncAttributeMaxDynamicSharedMemorySize, LSMEM);

    __half *pSeg, *pWH, *pB1, *pM, *pCT, *pA;
    float *pBias, *pH2;
    cudaGetSymbolAddress((void**)&pSeg, g_seg);
    cudaGetSymbolAddress((void**)&pWH, g_WH);
    cudaGetSymbolAddress((void**)&pB1, g_B1);
    cudaGetSymbolAddress((void**)&pM,  g_M);
    cudaGetSymbolAddress((void**)&pCT, g_CT);
    cudaGetSymbolAddress((void**)&pA,  g_A);
    cudaGetSymbolAddress((void**)&pBias, g_biasC);
    cudaGetSymbolAddress((void**)&pH2, g_H2);

    // merged prepass
    prep_all_k<<<1024, 256>>>(seg, hw1, hw3, lcW, lvW, gcW, gvW, lcb, lvb, gcb, gvb);

    // 1) h2
    h2_k<<<dim3(Bb * Nn, 4), dim3(128, 8)>>>(se, hw2, hb2);

    // 2) h1 = relu(seg @ w1 + b1) * h2
    mgemm(pSeg, pWH + OFF_HW1, hb1, pH2, pB1,
          512, 512, 512, 512, Nn, 0, 262144L, BLD, 512, 2 | 8);

    // 3) m = relu(h1m @ w3 + b3)
    mgemm(pB1, pWH + OFF_HW3, hb3, nullptr, pM,
          512, 512, 512, 512, Nn, BLD, 262144L, BLD, 512, 2);

    // 4) local NL: projection + band-pruned MMA attention
    for (int s = 0; s < 2; s++) {
        mgemm(pM, pWH + OFF_LCV + (long)s * 786432, pBias + s * 1536, nullptr, pCT,
              1536, 512, 512, 1536, Nn, BLD, 2L * 786432, CTN, 3072, 0);
        local_attn_k<<<dim3(4, Bb * Hh, Nn), 256, LSMEM>>>(mask);
    }

    // 5) segment attention weights
    satt_k<<<Bb, dim3(256, 4)>>>(se, sw1, sw2, out + BLD);

    // 6) aggregate
    agg_k<<<2048, 256>>>();

    // 7) global NL: projection + flash attention
    for (int s = 0; s < 2; s++) {
        mgemm(pA, pWH + OFF_GCV + (long)s * 786432, pBias + (6 + s) * 1536, nullptr, pCT,
              1536, 512, 512, 1536, 1, 0, 0, 0, 0, 0);
        flash_k<<<dim3(4, Bb * Hh), 256, FSMEM>>>(mask, (s == 1) ? out : nullptr);
    }
}